// round 10
// baseline (speedup 1.0000x reference)
#include <cuda_runtime.h>
#include <math.h>

#define L_SEQ 32768
#define H_DIM 128
#define P_DIM 256
#define CHUNK 64
#define NCHUNK (L_SEQ / CHUNK)   // 512
#define PTILE 64

typedef unsigned long long u64;

// ---------- f32x2 packed-FMA helpers ----------
__device__ __forceinline__ u64 s5_pack2(float lo, float hi) {
    u64 r;
    asm("mov.b64 %0, {%1,%2};" : "=l"(r) : "f"(lo), "f"(hi));
    return r;
}
__device__ __forceinline__ float2 s5_unpack2(u64 v) {
    float2 f;
    asm("mov.b64 {%0,%1}, %2;" : "=f"(f.x), "=f"(f.y) : "l"(v));
    return f;
}
__device__ __forceinline__ u64 s5_fma2(u64 a, u64 b, u64 c) {
    u64 d;
    asm("fma.rn.f32x2 %0, %1, %2, %3;" : "=l"(d) : "l"(a), "l"(b), "l"(c));
    return d;
}

// ---------- cp.async helpers ----------
__device__ __forceinline__ void s5_cp16(void* dst, const void* src) {
    unsigned d = (unsigned)__cvta_generic_to_shared(dst);
    asm volatile("cp.async.cg.shared.global [%0], [%1], 16;" :: "r"(d), "l"(src));
}
__device__ __forceinline__ void s5_cpcommit() {
    asm volatile("cp.async.commit_group;");
}
template <int N>
__device__ __forceinline__ void s5_cpwait() {
    asm volatile("cp.async.wait_group %0;" :: "n"(N));
}

// ---------- fast math (validated ranges) ----------
__device__ __forceinline__ float s5_exp_small(float x) {   // x in [-0.06, 0]
    return fmaf(x, fmaf(x, fmaf(x, fmaf(x, 0.041666667f, 0.16666667f), 0.5f), 1.0f), 1.0f);
}
// sincos for x in [0, ~5200], with exact low-order phase addend xlo applied
// after Cody-Waite reduction (fma-residual path keeps phase err ~1e-7 rad).
__device__ __forceinline__ void s5_sincos2(float x, float xlo, float& s_out, float& c_out) {
    float kf = rintf(x * 0.636619772f);                 // 2/pi
    float r = fmaf(-kf, 1.57079637f, x);
    r = fmaf(kf, 4.37113900e-8f, r);
    r += xlo;
    int q = (int)kf;
    float r2 = r * r;
    float sp = fmaf(r2, fmaf(r2, fmaf(r2, 2.7557314e-6f, -1.9841270e-4f),
                             8.3333310e-3f), -0.16666667f);
    sp = fmaf(r * r2, sp, r);
    float cp = fmaf(r2, fmaf(r2, fmaf(r2, 2.4801587e-5f, -1.3888889e-3f),
                             4.1666668e-2f), -0.5f);
    cp = fmaf(r2, cp, 1.0f);
    bool swp = (q & 1);
    float ss = swp ? cp : sp;
    float cc = swp ? sp : cp;
    if (q & 2) ss = -ss;
    if ((q + 1) & 2) cc = -cc;
    s_out = ss; c_out = cc;
}
__device__ __forceinline__ void s5_sincos(float x, float& s_out, float& c_out) {
    s5_sincos2(x, 0.0f, s_out, c_out);
}

// ---------- scratch (static device memory; no allocations) ----------
__device__ __align__(16) float2 sc_xloc[(size_t)L_SEQ * P_DIM];   // 64 MB (only per-element array left)
__device__ __align__(16) float2 sc_Achunk[NCHUNK * P_DIM];
__device__ __align__(16) float2 sc_xend[NCHUNK * P_DIM];
__device__ __align__(16) float2 sc_carry[NCHUNK * P_DIM];
__device__ __align__(16) float2 sc_S[NCHUNK * CHUNK];             // per-chunk dt prefix sums (hi, lo)
__device__ __align__(16) float4 sc_ab4[P_DIM];                    // (alpha, beta_hi, beta_lo, 0)
// Permuted operands: within each 64-col tile, loc -> column tx + 16*(2g+h5)
// so one float4 at [g*32 + tx*2] yields columns j=2g and j=2g+1 for thread tx.
__device__ __align__(16) float2 sc_Bt2[H_DIM * P_DIM];            // [h][tile][perm64]
__device__ __align__(16) float2 sc_Ct2[P_DIM * H_DIM];            // [p][perm128]

// ---------- S0: pack/permute B and C; per-p discretization params ----------
__global__ void s5_k0_pack(const float* __restrict__ Br, const float* __restrict__ Bi,
                           const float* __restrict__ Cr, const float* __restrict__ Ci,
                           const float* __restrict__ Lre, const float* __restrict__ Lim,
                           const float* __restrict__ logstep) {
    int idx = blockIdx.x * blockDim.x + threadIdx.x;
    if (idx < H_DIM * P_DIM) {
        {   // Bt2
            int h = idx >> 8;
            int rest = idx & 255;
            int t = rest >> 6;
            int loc = rest & 63;
            int g = loc >> 5, rem = loc & 31;
            int tx = rem >> 1, h5 = rem & 1;
            int p = t * 64 + tx + 16 * (2 * g + h5);
            sc_Bt2[idx] = make_float2(Br[p * H_DIM + h], Bi[p * H_DIM + h]);
        }
        {   // Ct2
            int p = idx >> 7;
            int loc = idx & 127;
            int g = loc >> 5, rem = loc & 31;
            int tx = rem >> 1, h5 = rem & 1;
            int h = tx + 16 * (2 * g + h5);
            sc_Ct2[idx] = make_float2(Cr[h * P_DIM + p], Ci[h * P_DIM + p]);
        }
        if (idx < P_DIM) {
            float step = expf(logstep[idx]);
            float a  = Lre[idx] * step;
            float bh = Lim[idx] * step;
            float bl = fmaf(Lim[idx], step, -bh);     // exact product residual
            sc_ab4[idx] = make_float4(a, bh, bl, 0.0f);
        }
    }
}

// ---------- S0b: per-chunk dt prefix sums in fp64, stored hi/lo ----------
__global__ void s5_kS_prefix(const float* __restrict__ dts) {
    __shared__ double s[CHUNK];
    int c = blockIdx.x, t = threadIdx.x;
    s[t] = (double)dts[c * CHUNK + t];
    __syncthreads();
#pragma unroll
    for (int off = 1; off < CHUNK; off <<= 1) {
        double add = (t >= off) ? s[t - off] : 0.0;
        __syncthreads();
        s[t] += add;
        __syncthreads();
    }
    double Sd = s[t];
    float hi = (float)Sd;
    float lo = (float)(Sd - (double)hi);
    sc_S[c * CHUNK + t] = make_float2(hi, lo);
}

// ---------- S1: Bu = u @ B^T (complex), then 4-way-parallel local scan ----------
// Block: 64 L-rows x 64 P-cols, 256 threads. Grid: (4, 512).
__global__ __launch_bounds__(256, 2) void s5_k1_gemm_scan(
    const float* __restrict__ u, const float* __restrict__ dts,
    const float* __restrict__ Lre, const float* __restrict__ Lim,
    const float* __restrict__ logstep) {
    __shared__ __align__(16) char smem[49152];
    float*  uBuf0 = (float*)smem;                     // 8 KB
    float*  uBuf1 = (float*)(smem + 8192);            // 8 KB
    float2* bBuf0 = (float2*)(smem + 16384);          // 16 KB
    float2* bBuf1 = (float2*)(smem + 32768);          // 16 KB
    // scan-phase aliases
    float2* Bu    = (float2*)smem;                    // 32 KB (64x64 f2)
    float*  dt_s  = (float*)(smem + 32768);           // 256 B
    float2* As_s  = (float2*)(smem + 33024);          // 2 KB
    float2* xs_s2 = (float2*)(smem + 35072);          // 2 KB

    int tid = threadIdx.x;
    int tx = tid & 15, ty = tid >> 4;
    int l0 = blockIdx.y * CHUNK;
    int p0 = blockIdx.x * PTILE;

    u64 acc[4][4];
#pragma unroll
    for (int i = 0; i < 4; i++)
#pragma unroll
        for (int j = 0; j < 4; j++) acc[i][j] = 0ULL;

    auto stage = [&](int s, int b) {
        int h0 = s * 32;
        float*  ub = b ? uBuf1 : uBuf0;
        float2* bb = b ? bBuf1 : bBuf0;
#pragma unroll
        for (int e = 0; e < 2; e++) {
            int idx = e * 256 + tid;
            int r = idx >> 3, q = idx & 7;
            s5_cp16(&ub[r * 32 + q * 4], &u[(size_t)(l0 + r) * H_DIM + h0 + q * 4]);
        }
#pragma unroll
        for (int e = 0; e < 4; e++) {
            int idx = e * 256 + tid;
            int kk = idx >> 5, q = idx & 31;
            s5_cp16(&bb[kk * PTILE + q * 2], &sc_Bt2[(h0 + kk) * P_DIM + p0 + q * 2]);
        }
        s5_cpcommit();
    };

    stage(0, 0);
    stage(1, 1);
#pragma unroll
    for (int s = 0; s < 4; s++) {
        if (s < 3) s5_cpwait<1>(); else s5_cpwait<0>();
        __syncthreads();
        const float*  ub = (s & 1) ? uBuf1 : uBuf0;
        const float2* bb = (s & 1) ? bBuf1 : bBuf0;
#pragma unroll
        for (int kk = 0; kk < 32; kk += 2) {
            u64 ua0[4], ua1[4];
#pragma unroll
            for (int i = 0; i < 4; i++) {
                float2 uv = *reinterpret_cast<const float2*>(&ub[(ty + 16 * i) * 32 + kk]);
                ua0[i] = s5_pack2(uv.x, uv.x);
                ua1[i] = s5_pack2(uv.y, uv.y);
            }
            u64 bv0[4], bv1[4];
#pragma unroll
            for (int g = 0; g < 2; g++) {
                ulonglong2 t0 = *reinterpret_cast<const ulonglong2*>(&bb[kk * PTILE + g * 32 + tx * 2]);
                bv0[2 * g] = t0.x; bv0[2 * g + 1] = t0.y;
                ulonglong2 t1 = *reinterpret_cast<const ulonglong2*>(&bb[(kk + 1) * PTILE + g * 32 + tx * 2]);
                bv1[2 * g] = t1.x; bv1[2 * g + 1] = t1.y;
            }
#pragma unroll
            for (int i = 0; i < 4; i++)
#pragma unroll
                for (int j = 0; j < 4; j++) {
                    acc[i][j] = s5_fma2(ua0[i], bv0[j], acc[i][j]);
                    acc[i][j] = s5_fma2(ua1[i], bv1[j], acc[i][j]);
                }
        }
        __syncthreads();
        if (s + 2 < 4) stage(s + 2, s & 1);
    }

    // write Bu tile + dt into smem (conflict-free pattern; p = tx + 16*j)
#pragma unroll
    for (int i = 0; i < 4; i++)
#pragma unroll
        for (int j = 0; j < 4; j++)
            Bu[(ty + 16 * i) * PTILE + tx + 16 * j] = s5_unpack2(acc[i][j]);
    if (tid < CHUNK) dt_s[tid] = dts[l0 + tid];
    __syncthreads();

    // ---- parallel local scan: 64 p-columns x 4 segments of 16 steps ----
    int p   = tid & 63;
    int seg = tid >> 6;
    int gp  = p0 + p;
    int lb  = seg * 16;
    float lre = Lre[gp], lim = Lim[gp];
    float step = expf(logstep[gp]);
    float inv = 1.0f / (lre * lre + lim * lim);

    float xrA[16], xiA[16], ArA[16], AiA[16];
    {
        float xr = 0.f, xi = 0.f, Ar = 1.f, Ai = 0.f;
#pragma unroll
        for (int j = 0; j < 16; j++) {
            float d = dt_s[lb + j] * step;
            float ee = s5_exp_small(lre * d);
            float sn, cs;
            s5_sincos(lim * d, sn, cs);
            float ar = ee * cs, ai = ee * sn;
            float arm1 = ar - 1.0f;
            float gr = (arm1 * lre + ai * lim) * inv;
            float gi = (ai * lre - arm1 * lim) * inv;
            float2 bu = Bu[(lb + j) * PTILE + p];
            float br  = gr * bu.x - gi * bu.y;
            float bi2 = gr * bu.y + gi * bu.x;
            float nxr = ar * xr - ai * xi + br;
            float nxi = ar * xi + ai * xr + bi2;
            xr = nxr; xi = nxi;
            float nAr = ar * Ar - ai * Ai;
            float nAi = ar * Ai + ai * Ar;
            Ar = nAr; Ai = nAi;
            xrA[j] = xr; xiA[j] = xi; ArA[j] = Ar; AiA[j] = Ai;
        }
        As_s[seg * 64 + p]  = make_float2(Ar, Ai);
        xs_s2[seg * 64 + p] = make_float2(xr, xi);
    }
    __syncthreads();

    float cr = 0.f, ci = 0.f, pr = 1.f, pi = 0.f;
    for (int s = 0; s < seg; s++) {
        float2 A  = As_s[s * 64 + p];
        float2 xe = xs_s2[s * 64 + p];
        float ncr = A.x * cr - A.y * ci + xe.x;
        float nci = A.x * ci + A.y * cr + xe.y;
        cr = ncr; ci = nci;
        float npr = A.x * pr - A.y * pi;
        float npi = A.x * pi + A.y * pr;
        pr = npr; pi = npi;
    }

    // store chunk-relative states only (Acum recomputed analytically in k3)
#pragma unroll
    for (int j = 0; j < 16; j++) {
        float xgR = ArA[j] * cr - AiA[j] * ci + xrA[j];
        float xgI = ArA[j] * ci + AiA[j] * cr + xiA[j];
        sc_xloc[(size_t)(l0 + lb + j) * P_DIM + gp] = make_float2(xgR, xgI);
    }
    if (seg == 3) {
        float AgR = pr * ArA[15] - pi * AiA[15];
        float AgI = pr * AiA[15] + pi * ArA[15];
        float xeR = ArA[15] * cr - AiA[15] * ci + xrA[15];
        float xeI = ArA[15] * ci + AiA[15] * cr + xiA[15];
        sc_Achunk[blockIdx.y * P_DIM + gp] = make_float2(AgR, AgI);
        sc_xend[blockIdx.y * P_DIM + gp]   = make_float2(xeR, xeI);
    }
}

// ---------- S2: scan over chunk aggregates, batch-of-8 register prefetch ----------
__global__ void s5_k2_chunkscan() {
    int p = blockIdx.x * 32 + threadIdx.x;
    float gr = 0.f, gi = 0.f;
    sc_carry[p] = make_float2(0.f, 0.f);
    float2 A[8], X[8];
#pragma unroll
    for (int i = 0; i < 8; i++) {
        A[i] = sc_Achunk[i * P_DIM + p];
        X[i] = sc_xend[i * P_DIM + p];
    }
    for (int b = 0; b < NCHUNK; b += 8) {
        float2 An[8], Xn[8];
        if (b + 8 < NCHUNK) {
#pragma unroll
            for (int i = 0; i < 8; i++) {
                An[i] = sc_Achunk[(b + 8 + i) * P_DIM + p];
                Xn[i] = sc_xend[(b + 8 + i) * P_DIM + p];
            }
        }
#pragma unroll
        for (int i = 0; i < 8; i++) {
            int c = b + i;
            float nr = A[i].x * gr - A[i].y * gi + X[i].x;
            float ni = A[i].x * gi + A[i].y * gr + X[i].y;
            gr = nr; gi = ni;
            if (c + 1 < NCHUNK) sc_carry[(c + 1) * P_DIM + p] = make_float2(gr, gi);
        }
#pragma unroll
        for (int i = 0; i < 8; i++) { A[i] = An[i]; X[i] = Xn[i]; }
    }
}

// ---------- S3: analytic-Acum fixup + y = 2*Re(x @ C^T) + D*u ----------
// Block: 64 rows x 128 H, 256 threads. 16 K-slices of 16 p each.
// Acum(r,p) = exp(alpha*S_r) * cis(beta*S_r) computed from hi/lo pairs.
__global__ __launch_bounds__(256, 2) void s5_k3_fixup_gemm(
    const float* __restrict__ u, const float* __restrict__ D, float* __restrict__ out) {
    __shared__ __align__(16) char smem[49152];
    float2* xBuf0 = (float2*)smem;                    // 8 KB (64x16)
    float2* xBuf1 = (float2*)(smem + 8192);           // 8 KB
    float2* cBuf0 = (float2*)(smem + 16384);          // 16 KB (16x128)
    float2* cBuf1 = (float2*)(smem + 32768);          // 16 KB

    int tid = threadIdx.x, tx = tid & 15, ty = tid >> 4;
    int chunk = blockIdx.x;
    int l0 = chunk * CHUNK;

    u64 acc[4][8];
#pragma unroll
    for (int i = 0; i < 4; i++)
#pragma unroll
        for (int j = 0; j < 8; j++) acc[i][j] = 0ULL;

    // per-thread row prefix sums: r = 16e + ty, fixed for the whole block
    float2 Sr[4];
#pragma unroll
    for (int e = 0; e < 4; e++)
        Sr[e] = sc_S[chunk * CHUNK + 16 * e + ty];

    float2 pX[4], cC;
    float4 ab;
    auto ldgX = [&](int s) {
        int p0 = s * 16;
#pragma unroll
        for (int e = 0; e < 4; e++)
            pX[e] = sc_xloc[(size_t)(l0 + 16 * e + ty) * P_DIM + p0 + tx];
        cC = sc_carry[chunk * P_DIM + p0 + tx];
        ab = sc_ab4[p0 + tx];
    };
    auto stX = [&](int b) {
        float2* xb = b ? xBuf1 : xBuf0;
#pragma unroll
        for (int e = 0; e < 4; e++) {
            float Sh = Sr[e].x, Sl = Sr[e].y;
            float ph = ab.y * Sh;
            float pl = fmaf(ab.y, Sh, -ph);           // exact product residual
            pl = fmaf(ab.y, Sl, pl);
            pl = fmaf(ab.z, Sh, pl);
            float amp = __expf(ab.x * Sh);
            float sn, cs;
            s5_sincos2(ph, pl, sn, cs);
            float Ar = amp * cs, Ai = amp * sn;
            float2 x;
            x.x = Ar * cC.x - Ai * cC.y + pX[e].x;
            x.y = Ar * cC.y + Ai * cC.x + pX[e].y;
            xb[(16 * e + ty) * 16 + tx] = x;
        }
    };
    auto cpC = [&](int s, int b) {
        int p0 = s * 16;
        float2* cb = b ? cBuf1 : cBuf0;
#pragma unroll
        for (int e = 0; e < 4; e++) {
            int idx = e * 256 + tid;
            int kk = idx >> 6, q = idx & 63;
            s5_cp16(&cb[kk * H_DIM + q * 2], &sc_Ct2[(p0 + kk) * H_DIM + q * 2]);
        }
        s5_cpcommit();
    };

    ldgX(0);
    cpC(0, 0);
    for (int s = 0; s < 16; s++) {
        int b = s & 1;
        stX(b);
        if (s < 15) { ldgX(s + 1); cpC(s + 1, b ^ 1); }
        if (s < 15) s5_cpwait<1>(); else s5_cpwait<0>();
        __syncthreads();
        const float2* xb = b ? xBuf1 : xBuf0;
        const float2* cb = b ? cBuf1 : cBuf0;
#pragma unroll
        for (int kk = 0; kk < 16; kk++) {
            u64 xv[4], cv[8];
#pragma unroll
            for (int i = 0; i < 4; i++)
                xv[i] = *reinterpret_cast<const u64*>(&xb[(ty + 16 * i) * 16 + kk]);
#pragma unroll
            for (int g = 0; g < 4; g++) {
                ulonglong2 t = *reinterpret_cast<const ulonglong2*>(&cb[kk * H_DIM + g * 32 + tx * 2]);
                cv[2 * g] = t.x; cv[2 * g + 1] = t.y;
            }
#pragma unroll
            for (int i = 0; i < 4; i++)
#pragma unroll
                for (int j = 0; j < 8; j++)
                    acc[i][j] = s5_fma2(xv[i], cv[j], acc[i][j]);
        }
        __syncthreads();
    }

#pragma unroll
    for (int i = 0; i < 4; i++) {
        int l = l0 + ty + 16 * i;
#pragma unroll
        for (int j = 0; j < 8; j++) {
            int h = tx + 16 * j;
            float2 s = s5_unpack2(acc[i][j]);
            out[(size_t)l * H_DIM + h] = 2.0f * (s.x - s.y) + D[h] * u[(size_t)l * H_DIM + h];
        }
    }
}

extern "C" void kernel_launch(void* const* d_in, const int* in_sizes, int n_in,
                              void* d_out, int out_size) {
    const float* u       = (const float*)d_in[0];
    const float* dts     = (const float*)d_in[1];
    const float* Lre     = (const float*)d_in[2];
    const float* Lim     = (const float*)d_in[3];
    const float* logstep = (const float*)d_in[4];
    const float* Br      = (const float*)d_in[5];
    const float* Bi      = (const float*)d_in[6];
    const float* Cr      = (const float*)d_in[7];
    const float* Ci      = (const float*)d_in[8];
    const float* D       = (const float*)d_in[9];
    float* out = (float*)d_out;

    s5_k0_pack<<<(H_DIM * P_DIM + 255) / 256, 256>>>(Br, Bi, Cr, Ci, Lre, Lim, logstep);
    s5_kS_prefix<<<NCHUNK, CHUNK>>>(dts);
    dim3 g1(P_DIM / PTILE, L_SEQ / CHUNK);
    s5_k1_gemm_scan<<<g1, 256>>>(u, dts, Lre, Lim, logstep);
    s5_k2_chunkscan<<<8, 32>>>();
    s5_k3_fixup_gemm<<<L_SEQ / CHUNK, 256>>>(u, D, out);
}

// round 11
// speedup vs baseline: 1.0950x; 1.0950x over previous
#include <cuda_runtime.h>
#include <math.h>

#define L_SEQ 32768
#define H_DIM 128
#define P_DIM 256
#define CHUNK 64
#define NCHUNK (L_SEQ / CHUNK)   // 512
#define PTILE 64

typedef unsigned long long u64;

// ---------- f32x2 packed-FMA helpers ----------
__device__ __forceinline__ u64 s5_pack2(float lo, float hi) {
    u64 r;
    asm("mov.b64 %0, {%1,%2};" : "=l"(r) : "f"(lo), "f"(hi));
    return r;
}
__device__ __forceinline__ float2 s5_unpack2(u64 v) {
    float2 f;
    asm("mov.b64 {%0,%1}, %2;" : "=f"(f.x), "=f"(f.y) : "l"(v));
    return f;
}
__device__ __forceinline__ u64 s5_fma2(u64 a, u64 b, u64 c) {
    u64 d;
    asm("fma.rn.f32x2 %0, %1, %2, %3;" : "=l"(d) : "l"(a), "l"(b), "l"(c));
    return d;
}

// ---------- cp.async helpers ----------
__device__ __forceinline__ void s5_cp16(void* dst, const void* src) {
    unsigned d = (unsigned)__cvta_generic_to_shared(dst);
    asm volatile("cp.async.cg.shared.global [%0], [%1], 16;" :: "r"(d), "l"(src));
}
__device__ __forceinline__ void s5_cpcommit() {
    asm volatile("cp.async.commit_group;");
}
template <int N>
__device__ __forceinline__ void s5_cpwait() {
    asm volatile("cp.async.wait_group %0;" :: "n"(N));
}

// ---------- fast math (validated ranges) ----------
__device__ __forceinline__ float s5_exp_small(float x) {   // x in [-0.06, 0]
    return fmaf(x, fmaf(x, fmaf(x, fmaf(x, 0.041666667f, 0.16666667f), 0.5f), 1.0f), 1.0f);
}
// sincos with exact low-order phase addend applied post-reduction
__device__ __forceinline__ void s5_sincos2(float x, float xlo, float& s_out, float& c_out) {
    float kf = rintf(x * 0.636619772f);                 // 2/pi
    float r = fmaf(-kf, 1.57079637f, x);
    r = fmaf(kf, 4.37113900e-8f, r);
    r += xlo;
    int q = (int)kf;
    float r2 = r * r;
    float sp = fmaf(r2, fmaf(r2, fmaf(r2, 2.7557314e-6f, -1.9841270e-4f),
                             8.3333310e-3f), -0.16666667f);
    sp = fmaf(r * r2, sp, r);
    float cp = fmaf(r2, fmaf(r2, fmaf(r2, 2.4801587e-5f, -1.3888889e-3f),
                             4.1666668e-2f), -0.5f);
    cp = fmaf(r2, cp, 1.0f);
    bool swp = (q & 1);
    float ss = swp ? cp : sp;
    float cc = swp ? sp : cp;
    if (q & 2) ss = -ss;
    if ((q + 1) & 2) cc = -cc;
    s_out = ss; c_out = cc;
}
__device__ __forceinline__ void s5_sincos(float x, float& s_out, float& c_out) {
    s5_sincos2(x, 0.0f, s_out, c_out);
}

// ---------- scratch (static device memory; no allocations) ----------
__device__ __align__(16) float2 sc_xloc[(size_t)L_SEQ * P_DIM];   // 64 MB
__device__ __align__(16) float2 sc_AchunkT[P_DIM * NCHUNK];       // transposed [p][chunk]
__device__ __align__(16) float2 sc_xendT[P_DIM * NCHUNK];         // transposed [p][chunk]
__device__ __align__(16) float2 sc_carry[NCHUNK * P_DIM];         // [chunk][p] (k3-friendly)
__device__ __align__(16) float2 sc_S[NCHUNK * CHUNK];             // per-chunk dt prefix sums (hi, lo)
__device__ __align__(16) float4 sc_ab4[P_DIM];                    // (alpha, beta_hi, beta_lo, 0)
// Permuted operands: one float4 at [g*32 + tx*2] yields columns j=2g, 2g+1
__device__ __align__(16) float2 sc_Bt2[H_DIM * P_DIM];            // [h][tile][perm64]
__device__ __align__(16) float2 sc_Ct2[P_DIM * H_DIM];            // [p][perm128]

// ---------- S0: pack/permute B and C; per-p discretization params ----------
__global__ void s5_k0_pack(const float* __restrict__ Br, const float* __restrict__ Bi,
                           const float* __restrict__ Cr, const float* __restrict__ Ci,
                           const float* __restrict__ Lre, const float* __restrict__ Lim,
                           const float* __restrict__ logstep) {
    int idx = blockIdx.x * blockDim.x + threadIdx.x;
    if (idx < H_DIM * P_DIM) {
        {   // Bt2
            int h = idx >> 8;
            int rest = idx & 255;
            int t = rest >> 6;
            int loc = rest & 63;
            int g = loc >> 5, rem = loc & 31;
            int tx = rem >> 1, h5 = rem & 1;
            int p = t * 64 + tx + 16 * (2 * g + h5);
            sc_Bt2[idx] = make_float2(Br[p * H_DIM + h], Bi[p * H_DIM + h]);
        }
        {   // Ct2
            int p = idx >> 7;
            int loc = idx & 127;
            int g = loc >> 5, rem = loc & 31;
            int tx = rem >> 1, h5 = rem & 1;
            int h = tx + 16 * (2 * g + h5);
            sc_Ct2[idx] = make_float2(Cr[h * P_DIM + p], Ci[h * P_DIM + p]);
        }
        if (idx < P_DIM) {
            float step = expf(logstep[idx]);
            float a  = Lre[idx] * step;
            float bh = Lim[idx] * step;
            float bl = fmaf(Lim[idx], step, -bh);     // exact product residual
            sc_ab4[idx] = make_float4(a, bh, bl, 0.0f);
        }
    }
}

// ---------- S0b: per-chunk dt prefix sums in fp64, stored hi/lo ----------
__global__ void s5_kS_prefix(const float* __restrict__ dts) {
    __shared__ double s[CHUNK];
    int c = blockIdx.x, t = threadIdx.x;
    s[t] = (double)dts[c * CHUNK + t];
    __syncthreads();
#pragma unroll
    for (int off = 1; off < CHUNK; off <<= 1) {
        double add = (t >= off) ? s[t - off] : 0.0;
        __syncthreads();
        s[t] += add;
        __syncthreads();
    }
    double Sd = s[t];
    float hi = (float)Sd;
    float lo = (float)(Sd - (double)hi);
    sc_S[c * CHUNK + t] = make_float2(hi, lo);
}

// ---------- S1: Bu = u @ B^T (complex), then 4-way-parallel local scan ----------
// Block: 64 L-rows x 64 P-cols, 256 threads. Grid: (4, 512).
__global__ __launch_bounds__(256, 2) void s5_k1_gemm_scan(
    const float* __restrict__ u, const float* __restrict__ dts,
    const float* __restrict__ Lre, const float* __restrict__ Lim,
    const float* __restrict__ logstep) {
    __shared__ __align__(16) char smem[49152];
    float*  uBuf0 = (float*)smem;                     // 8 KB
    float*  uBuf1 = (float*)(smem + 8192);            // 8 KB
    float2* bBuf0 = (float2*)(smem + 16384);          // 16 KB
    float2* bBuf1 = (float2*)(smem + 32768);          // 16 KB
    // scan-phase aliases
    float2* Bu    = (float2*)smem;                    // 32 KB (64x64 f2)
    float*  dt_s  = (float*)(smem + 32768);           // 256 B
    float2* As_s  = (float2*)(smem + 33024);          // 2 KB
    float2* xs_s2 = (float2*)(smem + 35072);          // 2 KB

    int tid = threadIdx.x;
    int tx = tid & 15, ty = tid >> 4;
    int l0 = blockIdx.y * CHUNK;
    int p0 = blockIdx.x * PTILE;

    u64 acc[4][4];
#pragma unroll
    for (int i = 0; i < 4; i++)
#pragma unroll
        for (int j = 0; j < 4; j++) acc[i][j] = 0ULL;

    auto stage = [&](int s, int b) {
        int h0 = s * 32;
        float*  ub = b ? uBuf1 : uBuf0;
        float2* bb = b ? bBuf1 : bBuf0;
#pragma unroll
        for (int e = 0; e < 2; e++) {
            int idx = e * 256 + tid;
            int r = idx >> 3, q = idx & 7;
            s5_cp16(&ub[r * 32 + q * 4], &u[(size_t)(l0 + r) * H_DIM + h0 + q * 4]);
        }
#pragma unroll
        for (int e = 0; e < 4; e++) {
            int idx = e * 256 + tid;
            int kk = idx >> 5, q = idx & 31;
            s5_cp16(&bb[kk * PTILE + q * 2], &sc_Bt2[(h0 + kk) * P_DIM + p0 + q * 2]);
        }
        s5_cpcommit();
    };

    stage(0, 0);
    stage(1, 1);
#pragma unroll
    for (int s = 0; s < 4; s++) {
        if (s < 3) s5_cpwait<1>(); else s5_cpwait<0>();
        __syncthreads();
        const float*  ub = (s & 1) ? uBuf1 : uBuf0;
        const float2* bb = (s & 1) ? bBuf1 : bBuf0;
#pragma unroll
        for (int kk = 0; kk < 32; kk += 2) {
            u64 ua0[4], ua1[4];
#pragma unroll
            for (int i = 0; i < 4; i++) {
                float2 uv = *reinterpret_cast<const float2*>(&ub[(ty + 16 * i) * 32 + kk]);
                ua0[i] = s5_pack2(uv.x, uv.x);
                ua1[i] = s5_pack2(uv.y, uv.y);
            }
            u64 bv0[4], bv1[4];
#pragma unroll
            for (int g = 0; g < 2; g++) {
                ulonglong2 t0 = *reinterpret_cast<const ulonglong2*>(&bb[kk * PTILE + g * 32 + tx * 2]);
                bv0[2 * g] = t0.x; bv0[2 * g + 1] = t0.y;
                ulonglong2 t1 = *reinterpret_cast<const ulonglong2*>(&bb[(kk + 1) * PTILE + g * 32 + tx * 2]);
                bv1[2 * g] = t1.x; bv1[2 * g + 1] = t1.y;
            }
#pragma unroll
            for (int i = 0; i < 4; i++)
#pragma unroll
                for (int j = 0; j < 4; j++) {
                    acc[i][j] = s5_fma2(ua0[i], bv0[j], acc[i][j]);
                    acc[i][j] = s5_fma2(ua1[i], bv1[j], acc[i][j]);
                }
        }
        __syncthreads();
        if (s + 2 < 4) stage(s + 2, s & 1);
    }

    // write Bu tile + dt into smem (conflict-free pattern; p = tx + 16*j)
#pragma unroll
    for (int i = 0; i < 4; i++)
#pragma unroll
        for (int j = 0; j < 4; j++)
            Bu[(ty + 16 * i) * PTILE + tx + 16 * j] = s5_unpack2(acc[i][j]);
    if (tid < CHUNK) dt_s[tid] = dts[l0 + tid];
    __syncthreads();

    // ---- parallel local scan: 64 p-columns x 4 segments of 16 steps ----
    int p   = tid & 63;
    int seg = tid >> 6;
    int gp  = p0 + p;
    int lb  = seg * 16;
    float lre = Lre[gp], lim = Lim[gp];
    float step = expf(logstep[gp]);
    float inv = 1.0f / (lre * lre + lim * lim);

    float xrA[16], xiA[16], ArA[16], AiA[16];
    {
        float xr = 0.f, xi = 0.f, Ar = 1.f, Ai = 0.f;
#pragma unroll
        for (int j = 0; j < 16; j++) {
            float d = dt_s[lb + j] * step;
            float ee = s5_exp_small(lre * d);
            float sn, cs;
            s5_sincos(lim * d, sn, cs);
            float ar = ee * cs, ai = ee * sn;
            float arm1 = ar - 1.0f;
            float gr = (arm1 * lre + ai * lim) * inv;
            float gi = (ai * lre - arm1 * lim) * inv;
            float2 bu = Bu[(lb + j) * PTILE + p];
            float br  = gr * bu.x - gi * bu.y;
            float bi2 = gr * bu.y + gi * bu.x;
            float nxr = ar * xr - ai * xi + br;
            float nxi = ar * xi + ai * xr + bi2;
            xr = nxr; xi = nxi;
            float nAr = ar * Ar - ai * Ai;
            float nAi = ar * Ai + ai * Ar;
            Ar = nAr; Ai = nAi;
            xrA[j] = xr; xiA[j] = xi; ArA[j] = Ar; AiA[j] = Ai;
        }
        As_s[seg * 64 + p]  = make_float2(Ar, Ai);
        xs_s2[seg * 64 + p] = make_float2(xr, xi);
    }
    __syncthreads();

    float cr = 0.f, ci = 0.f, pr = 1.f, pi = 0.f;
    for (int s = 0; s < seg; s++) {
        float2 A  = As_s[s * 64 + p];
        float2 xe = xs_s2[s * 64 + p];
        float ncr = A.x * cr - A.y * ci + xe.x;
        float nci = A.x * ci + A.y * cr + xe.y;
        cr = ncr; ci = nci;
        float npr = A.x * pr - A.y * pi;
        float npi = A.x * pi + A.y * pr;
        pr = npr; pi = npi;
    }

    // store chunk-relative states only (Acum recomputed analytically in k3)
#pragma unroll
    for (int j = 0; j < 16; j++) {
        float xgR = ArA[j] * cr - AiA[j] * ci + xrA[j];
        float xgI = ArA[j] * ci + AiA[j] * cr + xiA[j];
        sc_xloc[(size_t)(l0 + lb + j) * P_DIM + gp] = make_float2(xgR, xgI);
    }
    if (seg == 3) {
        float AgR = pr * ArA[15] - pi * AiA[15];
        float AgI = pr * AiA[15] + pi * ArA[15];
        float xeR = ArA[15] * cr - AiA[15] * ci + xrA[15];
        float xeI = ArA[15] * ci + AiA[15] * cr + xiA[15];
        sc_AchunkT[gp * NCHUNK + blockIdx.y] = make_float2(AgR, AgI);
        sc_xendT[gp * NCHUNK + blockIdx.y]   = make_float2(xeR, xeI);
    }
}

// ---------- S2: PARALLEL scan over chunk aggregates ----------
// One block per p (grid 256), one thread per chunk (512). Hillis-Steele in smem.
__global__ __launch_bounds__(512) void s5_k2_chunkscan() {
    __shared__ __align__(16) float4 sdat[NCHUNK];   // (Ar, Ai, xr, xi)
    int p = blockIdx.x;
    int t = threadIdx.x;
    float2 A = sc_AchunkT[p * NCHUNK + t];
    float2 X = sc_xendT[p * NCHUNK + t];
    sdat[t] = make_float4(A.x, A.y, X.x, X.y);
    __syncthreads();
#pragma unroll
    for (int off = 1; off < NCHUNK; off <<= 1) {
        float4 prev;
        bool has = (t >= off);
        if (has) prev = sdat[t - off];
        __syncthreads();
        if (has) {
            float4 cur = sdat[t];
            float4 nw;
            nw.x = cur.x * prev.x - cur.y * prev.y;
            nw.y = cur.x * prev.y + cur.y * prev.x;
            nw.z = cur.x * prev.z - cur.y * prev.w + cur.z;
            nw.w = cur.x * prev.w + cur.y * prev.z + cur.w;
            sdat[t] = nw;
        }
        __syncthreads();
    }
    // exclusive carry: chunk t gets scan result of chunks [0, t-1]
    float2 carry = make_float2(0.f, 0.f);
    if (t > 0) {
        float4 v = sdat[t - 1];
        carry = make_float2(v.z, v.w);
    }
    sc_carry[t * P_DIM + p] = carry;
}

// ---------- S3: analytic-Acum fixup + y = 2*Re(x @ C^T) + D*u ----------
__global__ __launch_bounds__(256, 2) void s5_k3_fixup_gemm(
    const float* __restrict__ u, const float* __restrict__ D, float* __restrict__ out) {
    __shared__ __align__(16) char smem[49152];
    float2* xBuf0 = (float2*)smem;                    // 8 KB (64x16)
    float2* xBuf1 = (float2*)(smem + 8192);           // 8 KB
    float2* cBuf0 = (float2*)(smem + 16384);          // 16 KB (16x128)
    float2* cBuf1 = (float2*)(smem + 32768);          // 16 KB

    int tid = threadIdx.x, tx = tid & 15, ty = tid >> 4;
    int chunk = blockIdx.x;
    int l0 = chunk * CHUNK;

    u64 acc[4][8];
#pragma unroll
    for (int i = 0; i < 4; i++)
#pragma unroll
        for (int j = 0; j < 8; j++) acc[i][j] = 0ULL;

    float2 Sr[4];
#pragma unroll
    for (int e = 0; e < 4; e++)
        Sr[e] = sc_S[chunk * CHUNK + 16 * e + ty];

    float2 pX[4], cC;
    float4 ab;
    auto ldgX = [&](int s) {
        int p0 = s * 16;
#pragma unroll
        for (int e = 0; e < 4; e++)
            pX[e] = sc_xloc[(size_t)(l0 + 16 * e + ty) * P_DIM + p0 + tx];
        cC = sc_carry[chunk * P_DIM + p0 + tx];
        ab = sc_ab4[p0 + tx];
    };
    auto stX = [&](int b) {
        float2* xb = b ? xBuf1 : xBuf0;
#pragma unroll
        for (int e = 0; e < 4; e++) {
            float Sh = Sr[e].x, Sl = Sr[e].y;
            float ph = ab.y * Sh;
            float pl = fmaf(ab.y, Sh, -ph);           // exact product residual
            pl = fmaf(ab.y, Sl, pl);
            pl = fmaf(ab.z, Sh, pl);
            float amp = __expf(ab.x * Sh);
            float sn, cs;
            s5_sincos2(ph, pl, sn, cs);
            float Ar = amp * cs, Ai = amp * sn;
            float2 x;
            x.x = Ar * cC.x - Ai * cC.y + pX[e].x;
            x.y = Ar * cC.y + Ai * cC.x + pX[e].y;
            xb[(16 * e + ty) * 16 + tx] = x;
        }
    };
    auto cpC = [&](int s, int b) {
        int p0 = s * 16;
        float2* cb = b ? cBuf1 : cBuf0;
#pragma unroll
        for (int e = 0; e < 4; e++) {
            int idx = e * 256 + tid;
            int kk = idx >> 6, q = idx & 63;
            s5_cp16(&cb[kk * H_DIM + q * 2], &sc_Ct2[(p0 + kk) * H_DIM + q * 2]);
        }
        s5_cpcommit();
    };

    ldgX(0);
    cpC(0, 0);
    for (int s = 0; s < 16; s++) {
        int b = s & 1;
        stX(b);
        if (s < 15) { ldgX(s + 1); cpC(s + 1, b ^ 1); }
        if (s < 15) s5_cpwait<1>(); else s5_cpwait<0>();
        __syncthreads();
        const float2* xb = b ? xBuf1 : xBuf0;
        const float2* cb = b ? cBuf1 : cBuf0;
#pragma unroll
        for (int kk = 0; kk < 16; kk++) {
            u64 xv[4], cv[8];
#pragma unroll
            for (int i = 0; i < 4; i++)
                xv[i] = *reinterpret_cast<const u64*>(&xb[(ty + 16 * i) * 16 + kk]);
#pragma unroll
            for (int g = 0; g < 4; g++) {
                ulonglong2 t = *reinterpret_cast<const ulonglong2*>(&cb[kk * H_DIM + g * 32 + tx * 2]);
                cv[2 * g] = t.x; cv[2 * g + 1] = t.y;
            }
#pragma unroll
            for (int i = 0; i < 4; i++)
#pragma unroll
                for (int j = 0; j < 8; j++)
                    acc[i][j] = s5_fma2(xv[i], cv[j], acc[i][j]);
        }
        __syncthreads();
    }

#pragma unroll
    for (int i = 0; i < 4; i++) {
        int l = l0 + ty + 16 * i;
#pragma unroll
        for (int j = 0; j < 8; j++) {
            int h = tx + 16 * j;
            float2 s = s5_unpack2(acc[i][j]);
            out[(size_t)l * H_DIM + h] = 2.0f * (s.x - s.y) + D[h] * u[(size_t)l * H_DIM + h];
        }
    }
}

extern "C" void kernel_launch(void* const* d_in, const int* in_sizes, int n_in,
                              void* d_out, int out_size) {
    const float* u       = (const float*)d_in[0];
    const float* dts     = (const float*)d_in[1];
    const float* Lre     = (const float*)d_in[2];
    const float* Lim     = (const float*)d_in[3];
    const float* logstep = (const float*)d_in[4];
    const float* Br      = (const float*)d_in[5];
    const float* Bi      = (const float*)d_in[6];
    const float* Cr      = (const float*)d_in[7];
    const float* Ci      = (const float*)d_in[8];
    const float* D       = (const float*)d_in[9];
    float* out = (float*)d_out;

    s5_k0_pack<<<(H_DIM * P_DIM + 255) / 256, 256>>>(Br, Bi, Cr, Ci, Lre, Lim, logstep);
    s5_kS_prefix<<<NCHUNK, CHUNK>>>(dts);
    dim3 g1(P_DIM / PTILE, L_SEQ / CHUNK);
    s5_k1_gemm_scan<<<g1, 256>>>(u, dts, Lre, Lim, logstep);
    s5_k2_chunkscan<<<P_DIM, NCHUNK>>>();
    s5_k3_fixup_gemm<<<L_SEQ / CHUNK, 256>>>(u, D, out);
}

// round 12
// speedup vs baseline: 1.3685x; 1.2498x over previous
#include <cuda_runtime.h>
#include <math.h>

#define L_SEQ 32768
#define H_DIM 128
#define P_DIM 256
#define CHUNK 64
#define NCHUNK (L_SEQ / CHUNK)   // 512
#define PTILE 64

typedef unsigned long long u64;
typedef unsigned int u32;

// ---------- f32x2 packed-FMA helpers ----------
__device__ __forceinline__ u64 s5_pack2(float lo, float hi) {
    u64 r;
    asm("mov.b64 %0, {%1,%2};" : "=l"(r) : "f"(lo), "f"(hi));
    return r;
}
__device__ __forceinline__ float2 s5_unpack2(u64 v) {
    float2 f;
    asm("mov.b64 {%0,%1}, %2;" : "=f"(f.x), "=f"(f.y) : "l"(v));
    return f;
}
__device__ __forceinline__ u64 s5_fma2(u64 a, u64 b, u64 c) {
    u64 d;
    asm("fma.rn.f32x2 %0, %1, %2, %3;" : "=l"(d) : "l"(a), "l"(b), "l"(c));
    return d;
}

// ---------- cp.async helpers ----------
__device__ __forceinline__ void s5_cp16(void* dst, const void* src) {
    unsigned d = (unsigned)__cvta_generic_to_shared(dst);
    asm volatile("cp.async.cg.shared.global [%0], [%1], 16;" :: "r"(d), "l"(src));
}
__device__ __forceinline__ void s5_cpcommit() {
    asm volatile("cp.async.commit_group;");
}
template <int N>
__device__ __forceinline__ void s5_cpwait() {
    asm volatile("cp.async.wait_group %0;" :: "n"(N));
}

// ---------- tf32 helpers ----------
__device__ __forceinline__ float s5_tf32_rna(float v) {
    u32 h;
    asm("cvt.rna.tf32.f32 %0, %1;" : "=r"(h) : "f"(v));
    return __uint_as_float(h);
}
#define S5_MMA(d, a, b0v, b1v) \
    asm volatile("mma.sync.aligned.m16n8k8.row.col.f32.tf32.tf32.f32 " \
                 "{%0,%1,%2,%3},{%4,%5,%6,%7},{%8,%9},{%0,%1,%2,%3};" \
                 : "+f"((d)[0]), "+f"((d)[1]), "+f"((d)[2]), "+f"((d)[3]) \
                 : "r"((a)[0]), "r"((a)[1]), "r"((a)[2]), "r"((a)[3]), \
                   "r"(b0v), "r"(b1v))

// ---------- fast math (validated ranges) ----------
__device__ __forceinline__ float s5_exp_small(float x) {   // x in [-0.06, 0]
    return fmaf(x, fmaf(x, fmaf(x, fmaf(x, 0.041666667f, 0.16666667f), 0.5f), 1.0f), 1.0f);
}
__device__ __forceinline__ void s5_sincos2(float x, float xlo, float& s_out, float& c_out) {
    float kf = rintf(x * 0.636619772f);                 // 2/pi
    float r = fmaf(-kf, 1.57079637f, x);
    r = fmaf(kf, 4.37113900e-8f, r);
    r += xlo;
    int q = (int)kf;
    float r2 = r * r;
    float sp = fmaf(r2, fmaf(r2, fmaf(r2, 2.7557314e-6f, -1.9841270e-4f),
                             8.3333310e-3f), -0.16666667f);
    sp = fmaf(r * r2, sp, r);
    float cp = fmaf(r2, fmaf(r2, fmaf(r2, 2.4801587e-5f, -1.3888889e-3f),
                             4.1666668e-2f), -0.5f);
    cp = fmaf(r2, cp, 1.0f);
    bool swp = (q & 1);
    float ss = swp ? cp : sp;
    float cc = swp ? sp : cp;
    if (q & 2) ss = -ss;
    if ((q + 1) & 2) cc = -cc;
    s_out = ss; c_out = cc;
}
__device__ __forceinline__ void s5_sincos(float x, float& s_out, float& c_out) {
    s5_sincos2(x, 0.0f, s_out, c_out);
}

// ---------- scratch (static device memory; no allocations) ----------
__device__ __align__(16) float2 sc_xloc[(size_t)L_SEQ * P_DIM];   // 64 MB
__device__ __align__(16) float2 sc_AchunkT[P_DIM * NCHUNK];       // [p][chunk]
__device__ __align__(16) float2 sc_xendT[P_DIM * NCHUNK];         // [p][chunk]
__device__ __align__(16) float2 sc_carry[NCHUNK * P_DIM];         // [chunk][p]
__device__ __align__(16) float2 sc_S[NCHUNK * CHUNK];             // dt prefix sums (hi, lo)
__device__ __align__(16) float4 sc_ab4[P_DIM];                    // (alpha, beta_hi, beta_lo, 0)
__device__ __align__(16) float2 sc_Bt2[H_DIM * P_DIM];            // k1 operand (perm64)
// k3 tensor operand: W = [2*Cr ; -2*Ci], tf32-RNE rounded, mma-fragment-permuted:
// [slice s (16)][k8 (4)][h (128)][ (k&3)*2 + (k>>2) (8) ]
__device__ __align__(16) float sc_Wt[16 * 4 * H_DIM * 8];         // 256 KB

// ---------- S0: pack/permute operands; per-p discretization params ----------
__global__ void s5_k0_pack(const float* __restrict__ Br, const float* __restrict__ Bi,
                           const float* __restrict__ Cr, const float* __restrict__ Ci,
                           const float* __restrict__ Lre, const float* __restrict__ Lim,
                           const float* __restrict__ logstep) {
    int idx = blockIdx.x * blockDim.x + threadIdx.x;
    if (idx < H_DIM * P_DIM) {
        {   // Bt2 (k1 GEMM operand)
            int h = idx >> 8;
            int rest = idx & 255;
            int t = rest >> 6;
            int loc = rest & 63;
            int g = loc >> 5, rem = loc & 31;
            int tx = rem >> 1, h5 = rem & 1;
            int p = t * 64 + tx + 16 * (2 * g + h5);
            sc_Bt2[idx] = make_float2(Br[p * H_DIM + h], Bi[p * H_DIM + h]);
        }
        {   // Wt (k3 tensor operand), idx -> (h, p)
            int h = idx & 127, p = idx >> 7;
            int s = p >> 4, pp = p & 15;
            int c = pp & 7;
            int sub = (c & 3) * 2 + (c >> 2);
            int k8r = pp >> 3;          // re rows: k = pp
            int k8i = 2 + (pp >> 3);    // im rows: k = 16 + pp
            float cr = Cr[h * P_DIM + p];
            float ci = Ci[h * P_DIM + p];
            sc_Wt[s * 4096 + k8r * 1024 + h * 8 + sub] = s5_tf32_rna(2.0f * cr);
            sc_Wt[s * 4096 + k8i * 1024 + h * 8 + sub] = s5_tf32_rna(-2.0f * ci);
        }
        if (idx < P_DIM) {
            float step = expf(logstep[idx]);
            float a  = Lre[idx] * step;
            float bh = Lim[idx] * step;
            float bl = fmaf(Lim[idx], step, -bh);
            sc_ab4[idx] = make_float4(a, bh, bl, 0.0f);
        }
    }
}

// ---------- S0b: per-chunk dt prefix sums in fp64, stored hi/lo ----------
__global__ void s5_kS_prefix(const float* __restrict__ dts) {
    __shared__ double s[CHUNK];
    int c = blockIdx.x, t = threadIdx.x;
    s[t] = (double)dts[c * CHUNK + t];
    __syncthreads();
#pragma unroll
    for (int off = 1; off < CHUNK; off <<= 1) {
        double add = (t >= off) ? s[t - off] : 0.0;
        __syncthreads();
        s[t] += add;
        __syncthreads();
    }
    double Sd = s[t];
    float hi = (float)Sd;
    float lo = (float)(Sd - (double)hi);
    sc_S[c * CHUNK + t] = make_float2(hi, lo);
}

// ---------- S1: Bu = u @ B^T (complex), then 4-way-parallel local scan ----------
__global__ __launch_bounds__(256, 2) void s5_k1_gemm_scan(
    const float* __restrict__ u, const float* __restrict__ dts,
    const float* __restrict__ Lre, const float* __restrict__ Lim,
    const float* __restrict__ logstep) {
    __shared__ __align__(16) char smem[49152];
    float*  uBuf0 = (float*)smem;
    float*  uBuf1 = (float*)(smem + 8192);
    float2* bBuf0 = (float2*)(smem + 16384);
    float2* bBuf1 = (float2*)(smem + 32768);
    float2* Bu    = (float2*)smem;                    // alias
    float*  dt_s  = (float*)(smem + 32768);
    float2* As_s  = (float2*)(smem + 33024);
    float2* xs_s2 = (float2*)(smem + 35072);

    int tid = threadIdx.x;
    int tx = tid & 15, ty = tid >> 4;
    int l0 = blockIdx.y * CHUNK;
    int p0 = blockIdx.x * PTILE;

    u64 acc[4][4];
#pragma unroll
    for (int i = 0; i < 4; i++)
#pragma unroll
        for (int j = 0; j < 4; j++) acc[i][j] = 0ULL;

    auto stage = [&](int s, int b) {
        int h0 = s * 32;
        float*  ub = b ? uBuf1 : uBuf0;
        float2* bb = b ? bBuf1 : bBuf0;
#pragma unroll
        for (int e = 0; e < 2; e++) {
            int idx = e * 256 + tid;
            int r = idx >> 3, q = idx & 7;
            s5_cp16(&ub[r * 32 + q * 4], &u[(size_t)(l0 + r) * H_DIM + h0 + q * 4]);
        }
#pragma unroll
        for (int e = 0; e < 4; e++) {
            int idx = e * 256 + tid;
            int kk = idx >> 5, q = idx & 31;
            s5_cp16(&bb[kk * PTILE + q * 2], &sc_Bt2[(h0 + kk) * P_DIM + p0 + q * 2]);
        }
        s5_cpcommit();
    };

    stage(0, 0);
    stage(1, 1);
#pragma unroll
    for (int s = 0; s < 4; s++) {
        if (s < 3) s5_cpwait<1>(); else s5_cpwait<0>();
        __syncthreads();
        const float*  ub = (s & 1) ? uBuf1 : uBuf0;
        const float2* bb = (s & 1) ? bBuf1 : bBuf0;
#pragma unroll
        for (int kk = 0; kk < 32; kk += 2) {
            u64 ua0[4], ua1[4];
#pragma unroll
            for (int i = 0; i < 4; i++) {
                float2 uv = *reinterpret_cast<const float2*>(&ub[(ty + 16 * i) * 32 + kk]);
                ua0[i] = s5_pack2(uv.x, uv.x);
                ua1[i] = s5_pack2(uv.y, uv.y);
            }
            u64 bv0[4], bv1[4];
#pragma unroll
            for (int g = 0; g < 2; g++) {
                ulonglong2 t0 = *reinterpret_cast<const ulonglong2*>(&bb[kk * PTILE + g * 32 + tx * 2]);
                bv0[2 * g] = t0.x; bv0[2 * g + 1] = t0.y;
                ulonglong2 t1 = *reinterpret_cast<const ulonglong2*>(&bb[(kk + 1) * PTILE + g * 32 + tx * 2]);
                bv1[2 * g] = t1.x; bv1[2 * g + 1] = t1.y;
            }
#pragma unroll
            for (int i = 0; i < 4; i++)
#pragma unroll
                for (int j = 0; j < 4; j++) {
                    acc[i][j] = s5_fma2(ua0[i], bv0[j], acc[i][j]);
                    acc[i][j] = s5_fma2(ua1[i], bv1[j], acc[i][j]);
                }
        }
        __syncthreads();
        if (s + 2 < 4) stage(s + 2, s & 1);
    }

#pragma unroll
    for (int i = 0; i < 4; i++)
#pragma unroll
        for (int j = 0; j < 4; j++)
            Bu[(ty + 16 * i) * PTILE + tx + 16 * j] = s5_unpack2(acc[i][j]);
    if (tid < CHUNK) dt_s[tid] = dts[l0 + tid];
    __syncthreads();

    int p   = tid & 63;
    int seg = tid >> 6;
    int gp  = p0 + p;
    int lb  = seg * 16;
    float lre = Lre[gp], lim = Lim[gp];
    float step = expf(logstep[gp]);
    float inv = 1.0f / (lre * lre + lim * lim);

    float xrA[16], xiA[16], ArA[16], AiA[16];
    {
        float xr = 0.f, xi = 0.f, Ar = 1.f, Ai = 0.f;
#pragma unroll
        for (int j = 0; j < 16; j++) {
            float d = dt_s[lb + j] * step;
            float ee = s5_exp_small(lre * d);
            float sn, cs;
            s5_sincos(lim * d, sn, cs);
            float ar = ee * cs, ai = ee * sn;
            float arm1 = ar - 1.0f;
            float gr = (arm1 * lre + ai * lim) * inv;
            float gi = (ai * lre - arm1 * lim) * inv;
            float2 bu = Bu[(lb + j) * PTILE + p];
            float br  = gr * bu.x - gi * bu.y;
            float bi2 = gr * bu.y + gi * bu.x;
            float nxr = ar * xr - ai * xi + br;
            float nxi = ar * xi + ai * xr + bi2;
            xr = nxr; xi = nxi;
            float nAr = ar * Ar - ai * Ai;
            float nAi = ar * Ai + ai * Ar;
            Ar = nAr; Ai = nAi;
            xrA[j] = xr; xiA[j] = xi; ArA[j] = Ar; AiA[j] = Ai;
        }
        As_s[seg * 64 + p]  = make_float2(Ar, Ai);
        xs_s2[seg * 64 + p] = make_float2(xr, xi);
    }
    __syncthreads();

    float cr = 0.f, ci = 0.f, pr = 1.f, pi = 0.f;
    for (int s = 0; s < seg; s++) {
        float2 A  = As_s[s * 64 + p];
        float2 xe = xs_s2[s * 64 + p];
        float ncr = A.x * cr - A.y * ci + xe.x;
        float nci = A.x * ci + A.y * cr + xe.y;
        cr = ncr; ci = nci;
        float npr = A.x * pr - A.y * pi;
        float npi = A.x * pi + A.y * pr;
        pr = npr; pi = npi;
    }

#pragma unroll
    for (int j = 0; j < 16; j++) {
        float xgR = ArA[j] * cr - AiA[j] * ci + xrA[j];
        float xgI = ArA[j] * ci + AiA[j] * cr + xiA[j];
        sc_xloc[(size_t)(l0 + lb + j) * P_DIM + gp] = make_float2(xgR, xgI);
    }
    if (seg == 3) {
        float AgR = pr * ArA[15] - pi * AiA[15];
        float AgI = pr * AiA[15] + pi * ArA[15];
        float xeR = ArA[15] * cr - AiA[15] * ci + xrA[15];
        float xeI = ArA[15] * ci + AiA[15] * cr + xiA[15];
        sc_AchunkT[gp * NCHUNK + blockIdx.y] = make_float2(AgR, AgI);
        sc_xendT[gp * NCHUNK + blockIdx.y]   = make_float2(xeR, xeI);
    }
}

// ---------- S2: PARALLEL scan over chunk aggregates ----------
__global__ __launch_bounds__(512) void s5_k2_chunkscan() {
    __shared__ __align__(16) float4 sdat[NCHUNK];
    int p = blockIdx.x;
    int t = threadIdx.x;
    float2 A = sc_AchunkT[p * NCHUNK + t];
    float2 X = sc_xendT[p * NCHUNK + t];
    sdat[t] = make_float4(A.x, A.y, X.x, X.y);
    __syncthreads();
#pragma unroll
    for (int off = 1; off < NCHUNK; off <<= 1) {
        float4 prev;
        bool has = (t >= off);
        if (has) prev = sdat[t - off];
        __syncthreads();
        if (has) {
            float4 cur = sdat[t];
            float4 nw;
            nw.x = cur.x * prev.x - cur.y * prev.y;
            nw.y = cur.x * prev.y + cur.y * prev.x;
            nw.z = cur.x * prev.z - cur.y * prev.w + cur.z;
            nw.w = cur.x * prev.w + cur.y * prev.z + cur.w;
            sdat[t] = nw;
        }
        __syncthreads();
    }
    float2 carry = make_float2(0.f, 0.f);
    if (t > 0) {
        float4 v = sdat[t - 1];
        carry = make_float2(v.z, v.w);
    }
    sc_carry[t * P_DIM + p] = carry;
}

// ---------- S3: analytic-Acum fixup + TENSOR readout y = X@W + D*u ----------
// X[64 x 512] = [xr | xi] split tf32 hi/lo; W = [2Cr; -2Ci] pre-packed tf32.
// 16 K-slices of 32 (16 re + 16 im). mma m16n8k8; warp grid 4(m) x 2(n).
__global__ __launch_bounds__(256, 2) void s5_k3_fixup_gemm(
    const float* __restrict__ u, const float* __restrict__ D, float* __restrict__ out) {
    __shared__ __align__(16) char smem[49152];
    float* xs  = (float*)smem;                        // X hi [0,2048) lo [2048,4096)
    float* wB0 = (float*)(smem + 16384);              // W slice buf 0 (16 KB)
    float* wB1 = (float*)(smem + 32768);              // W slice buf 1

    int tid = threadIdx.x, tx = tid & 15, ty = tid >> 4;
    int lane = tid & 31, wid = tid >> 5;
    int gid = lane >> 2, tig = lane & 3;
    int wm = wid & 3, wn = wid >> 2;
    int chunk = blockIdx.x;
    int l0 = chunk * CHUNK;

    float d[8][4];
#pragma unroll
    for (int j = 0; j < 8; j++)
#pragma unroll
        for (int i = 0; i < 4; i++) d[j][i] = 0.0f;

    float2 Sr[4];
#pragma unroll
    for (int e = 0; e < 4; e++)
        Sr[e] = sc_S[chunk * CHUNK + 16 * e + ty];

    float2 pX[4], cC;
    float4 ab;
    auto ldgX = [&](int s) {
        int p0 = s * 16;
#pragma unroll
        for (int e = 0; e < 4; e++)
            pX[e] = sc_xloc[(size_t)(l0 + 16 * e + ty) * P_DIM + p0 + tx];
        cC = sc_carry[chunk * P_DIM + p0 + tx];
        ab = sc_ab4[p0 + tx];
    };
    // fixup + tf32 split + permuted store: thread covers (rows 16e+ty, p-col tx)
    auto stX = [&]() {
#pragma unroll
        for (int e = 0; e < 4; e++) {
            float Sh = Sr[e].x, Sl = Sr[e].y;
            float ph = ab.y * Sh;
            float pl = fmaf(ab.y, Sh, -ph);
            pl = fmaf(ab.y, Sl, pl);
            pl = fmaf(ab.z, Sh, pl);
            float amp = __expf(ab.x * Sh);
            float sn, cs;
            s5_sincos2(ph, pl, sn, cs);
            float Ar = amp * cs, Ai = amp * sn;
            float xre = Ar * cC.x - Ai * cC.y + pX[e].x;
            float xim = Ar * cC.y + Ai * cC.x + pX[e].y;
            int row = 16 * e + ty;
            // re at k=tx, im at k=16+tx
#pragma unroll
            for (int comp = 0; comp < 2; comp++) {
                float v = comp ? xim : xre;
                int k = comp * 16 + tx;
                int c = k & 7;
                int off = (k >> 3) * 512 + row * 8 + (c & 3) * 2 + (c >> 2);
                float hi = s5_tf32_rna(v);
                xs[off] = hi;
                xs[2048 + off] = v - hi;
            }
        }
    };
    auto cpW = [&](int s, int b) {
        float* wb = b ? wB1 : wB0;
        const float* src = &sc_Wt[s * 4096];
#pragma unroll
        for (int e = 0; e < 4; e++) {
            int q = e * 256 + tid;        // 1024 x 16B chunks
            s5_cp16(&wb[q * 4], &src[q * 4]);
        }
        s5_cpcommit();
    };

    ldgX(0);
    cpW(0, 0);
    for (int s = 0; s < 16; s++) {
        int b = s & 1;
        stX();
        if (s < 15) { ldgX(s + 1); cpW(s + 1, b ^ 1); }
        if (s < 15) s5_cpwait<1>(); else s5_cpwait<0>();
        __syncthreads();
        const float* wb = b ? wB1 : wB0;
#pragma unroll
        for (int k8 = 0; k8 < 4; k8++) {
            int arow = wm * 16 + gid;
            float2 ah0 = *(const float2*)(xs + k8 * 512 + arow * 8 + tig * 2);
            float2 ah1 = *(const float2*)(xs + k8 * 512 + (arow + 8) * 8 + tig * 2);
            float2 al0 = *(const float2*)(xs + 2048 + k8 * 512 + arow * 8 + tig * 2);
            float2 al1 = *(const float2*)(xs + 2048 + k8 * 512 + (arow + 8) * 8 + tig * 2);
            u32 ahi[4] = {__float_as_uint(ah0.x), __float_as_uint(ah1.x),
                          __float_as_uint(ah0.y), __float_as_uint(ah1.y)};
            u32 alo[4] = {__float_as_uint(al0.x), __float_as_uint(al1.x),
                          __float_as_uint(al0.y), __float_as_uint(al1.y)};
#pragma unroll
            for (int j = 0; j < 8; j++) {
                float2 bv = *(const float2*)(wb + k8 * 1024 + (wn * 64 + j * 8 + gid) * 8 + tig * 2);
                u32 b0 = __float_as_uint(bv.x), b1 = __float_as_uint(bv.y);
                S5_MMA(d[j], ahi, b0, b1);
                S5_MMA(d[j], alo, b0, b1);
            }
        }
        __syncthreads();
    }

    // epilogue: y = acc + D*u  (2x folded into W)
#pragma unroll
    for (int j = 0; j < 8; j++) {
        int h = wn * 64 + j * 8 + tig * 2;
        float2 Dv = *(const float2*)(D + h);
        int r1 = l0 + wm * 16 + gid;
        int r2 = r1 + 8;
        float2 u1 = *(const float2*)(u + (size_t)r1 * H_DIM + h);
        float2 u2 = *(const float2*)(u + (size_t)r2 * H_DIM + h);
        float2 y1, y2;
        y1.x = d[j][0] + Dv.x * u1.x;
        y1.y = d[j][1] + Dv.y * u1.y;
        y2.x = d[j][2] + Dv.x * u2.x;
        y2.y = d[j][3] + Dv.y * u2.y;
        *(float2*)(out + (size_t)r1 * H_DIM + h) = y1;
        *(float2*)(out + (size_t)r2 * H_DIM + h) = y2;
    }
}

extern "C" void kernel_launch(void* const* d_in, const int* in_sizes, int n_in,
                              void* d_out, int out_size) {
    const float* u       = (const float*)d_in[0];
    const float* dts     = (const float*)d_in[1];
    const float* Lre     = (const float*)d_in[2];
    const float* Lim     = (const float*)d_in[3];
    const float* logstep = (const float*)d_in[4];
    const float* Br      = (const float*)d_in[5];
    const float* Bi      = (const float*)d_in[6];
    const float* Cr      = (const float*)d_in[7];
    const float* Ci      = (const float*)d_in[8];
    const float* D       = (const float*)d_in[9];
    float* out = (float*)d_out;

    s5_k0_pack<<<(H_DIM * P_DIM + 255) / 256, 256>>>(Br, Bi, Cr, Ci, Lre, Lim, logstep);
    s5_kS_prefix<<<NCHUNK, CHUNK>>>(dts);
    dim3 g1(P_DIM / PTILE, L_SEQ / CHUNK);
    s5_k1_gemm_scan<<<g1, 256>>>(u, dts, Lre, Lim, logstep);
    s5_k2_chunkscan<<<P_DIM, NCHUNK>>>();
    s5_k3_fixup_gemm<<<L_SEQ / CHUNK, 256>>>(u, D, out);
}

// round 13
// speedup vs baseline: 1.5316x; 1.1192x over previous
#include <cuda_runtime.h>
#include <math.h>

#define L_SEQ 32768
#define H_DIM 128
#define P_DIM 256
#define CHUNK 64
#define NCHUNK (L_SEQ / CHUNK)   // 512
#define PTILE 64
#define BUS 136                   // padded float stride of Bu tile in smem

typedef unsigned long long u64;
typedef unsigned int u32;

// ---------- cp.async helpers ----------
__device__ __forceinline__ void s5_cp16(void* dst, const void* src) {
    unsigned d = (unsigned)__cvta_generic_to_shared(dst);
    asm volatile("cp.async.cg.shared.global [%0], [%1], 16;" :: "r"(d), "l"(src));
}
__device__ __forceinline__ void s5_cpcommit() {
    asm volatile("cp.async.commit_group;");
}
template <int N>
__device__ __forceinline__ void s5_cpwait() {
    asm volatile("cp.async.wait_group %0;" :: "n"(N));
}

// ---------- tf32 helpers ----------
__device__ __forceinline__ float s5_tf32_rna(float v) {
    u32 h;
    asm("cvt.rna.tf32.f32 %0, %1;" : "=r"(h) : "f"(v));
    return __uint_as_float(h);
}
#define S5_MMA(d, a, b0v, b1v) \
    asm volatile("mma.sync.aligned.m16n8k8.row.col.f32.tf32.tf32.f32 " \
                 "{%0,%1,%2,%3},{%4,%5,%6,%7},{%8,%9},{%0,%1,%2,%3};" \
                 : "+f"((d)[0]), "+f"((d)[1]), "+f"((d)[2]), "+f"((d)[3]) \
                 : "r"((a)[0]), "r"((a)[1]), "r"((a)[2]), "r"((a)[3]), \
                   "r"(b0v), "r"(b1v))

// ---------- fast math (validated ranges) ----------
__device__ __forceinline__ float s5_exp_small(float x) {   // x in [-0.06, 0]
    return fmaf(x, fmaf(x, fmaf(x, fmaf(x, 0.041666667f, 0.16666667f), 0.5f), 1.0f), 1.0f);
}
__device__ __forceinline__ void s5_sincos2(float x, float xlo, float& s_out, float& c_out) {
    float kf = rintf(x * 0.636619772f);                 // 2/pi
    float r = fmaf(-kf, 1.57079637f, x);
    r = fmaf(kf, 4.37113900e-8f, r);
    r += xlo;
    int q = (int)kf;
    float r2 = r * r;
    float sp = fmaf(r2, fmaf(r2, fmaf(r2, 2.7557314e-6f, -1.9841270e-4f),
                             8.3333310e-3f), -0.16666667f);
    sp = fmaf(r * r2, sp, r);
    float cp = fmaf(r2, fmaf(r2, fmaf(r2, 2.4801587e-5f, -1.3888889e-3f),
                             4.1666668e-2f), -0.5f);
    cp = fmaf(r2, cp, 1.0f);
    bool swp = (q & 1);
    float ss = swp ? cp : sp;
    float cc = swp ? sp : cp;
    if (q & 2) ss = -ss;
    if ((q + 1) & 2) cc = -cc;
    s_out = ss; c_out = cc;
}
__device__ __forceinline__ void s5_sincos(float x, float& s_out, float& c_out) {
    s5_sincos2(x, 0.0f, s_out, c_out);
}

// ---------- scratch (static device memory; no allocations) ----------
__device__ __align__(16) float2 sc_xloc[(size_t)L_SEQ * P_DIM];   // 64 MB
__device__ __align__(16) float2 sc_AchunkT[P_DIM * NCHUNK];       // [p][chunk]
__device__ __align__(16) float2 sc_xendT[P_DIM * NCHUNK];         // [p][chunk]
__device__ __align__(16) float2 sc_carry[NCHUNK * P_DIM];         // [chunk][p]
__device__ __align__(16) float2 sc_S[NCHUNK * CHUNK];             // dt prefix sums (hi, lo)
__device__ __align__(16) float4 sc_ab4[P_DIM];                    // (alpha, beta_hi, beta_lo, 0)
// k3 tensor operand: W = [2*Cr ; -2*Ci], tf32-RNE, fragment-permuted
__device__ __align__(16) float sc_Wt[16 * 4 * H_DIM * 8];         // 256 KB
// k1 tensor operand: WB[ptile(4)][s(4)][k8(4)][col(128)][sub(8)], col = 2*pl + (re/im)
__device__ __align__(16) float sc_WB[4 * 4 * 4 * 128 * 8];        // 256 KB

// ---------- S0: pack/permute operands; per-p discretization params ----------
__global__ void s5_k0_pack(const float* __restrict__ Br, const float* __restrict__ Bi,
                           const float* __restrict__ Cr, const float* __restrict__ Ci,
                           const float* __restrict__ Lre, const float* __restrict__ Lim,
                           const float* __restrict__ logstep) {
    int idx = blockIdx.x * blockDim.x + threadIdx.x;
    if (idx < H_DIM * P_DIM) {
        int h = idx & 127, p = idx >> 7;
        {   // Wt (k3 operand): K dim = p (512 rows: re then im), col dim = h
            int s = p >> 4, pp = p & 15;
            int c = pp & 7;
            int sub = (c & 3) * 2 + (c >> 2);
            int k8r = pp >> 3;
            int k8i = 2 + (pp >> 3);
            float cr = Cr[h * P_DIM + p];
            float ci = Ci[h * P_DIM + p];
            sc_Wt[s * 4096 + k8r * 1024 + h * 8 + sub] = s5_tf32_rna(2.0f * cr);
            sc_Wt[s * 4096 + k8i * 1024 + h * 8 + sub] = s5_tf32_rna(-2.0f * ci);
        }
        {   // WB (k1 operand): K dim = h (128), col dim = 2*pl + comp
            int pt = p >> 6, pl = p & 63;
            int s = h >> 5, hk = h & 31;
            int k8 = hk >> 3, c = hk & 7;
            int sub = (c & 3) * 2 + (c >> 2);
            size_t base = ((size_t)(pt * 4 + s) * 4 + k8) * 1024;
            sc_WB[base + (pl * 2 + 0) * 8 + sub] = s5_tf32_rna(Br[p * H_DIM + h]);
            sc_WB[base + (pl * 2 + 1) * 8 + sub] = s5_tf32_rna(Bi[p * H_DIM + h]);
        }
        if (idx < P_DIM) {
            float step = expf(logstep[idx]);
            float a  = Lre[idx] * step;
            float bh = Lim[idx] * step;
            float bl = fmaf(Lim[idx], step, -bh);
            sc_ab4[idx] = make_float4(a, bh, bl, 0.0f);
        }
    }
}

// ---------- S0b: per-chunk dt prefix sums in fp64, stored hi/lo ----------
__global__ void s5_kS_prefix(const float* __restrict__ dts) {
    __shared__ double s[CHUNK];
    int c = blockIdx.x, t = threadIdx.x;
    s[t] = (double)dts[c * CHUNK + t];
    __syncthreads();
#pragma unroll
    for (int off = 1; off < CHUNK; off <<= 1) {
        double add = (t >= off) ? s[t - off] : 0.0;
        __syncthreads();
        s[t] += add;
        __syncthreads();
    }
    double Sd = s[t];
    float hi = (float)Sd;
    float lo = (float)(Sd - (double)hi);
    sc_S[c * CHUNK + t] = make_float2(hi, lo);
}

// ---------- S1: TENSOR Bu = u @ [Br|Bi]^T, then 4-way-parallel local scan ----------
// Block: 64 L-rows x 64 P-cols (=128 real cols), 256 threads. Grid: (4, 512).
// K=128 in 4 slices of 32; u split tf32 hi/lo; WB pre-packed RNE.
__global__ __launch_bounds__(256, 2) void s5_k1_gemm_scan(
    const float* __restrict__ u, const float* __restrict__ dts,
    const float* __restrict__ Lre, const float* __restrict__ Lim,
    const float* __restrict__ logstep) {
    __shared__ __align__(16) char smem[49152];
    float* xs  = (float*)smem;                        // u hi [0,8192) lo [8192,16384)
    float* wB0 = (float*)(smem + 16384);              // WB slice buf 0 (16 KB)
    float* wB1 = (float*)(smem + 32768);
    // scan-phase aliases
    float* Bu_s  = (float*)smem;                      // 64 x BUS floats (34816 B)
    float* dt_s  = (float*)(smem + 34816);            // 256 B
    float2* As_s  = (float2*)(smem + 35072);          // 2 KB
    float2* xs_s2 = (float2*)(smem + 37120);          // 2 KB

    int tid = threadIdx.x;
    int lane = tid & 31, wid = tid >> 5;
    int gid = lane >> 2, tig = lane & 3;
    int wm = wid & 3, wn = wid >> 2;
    int l0 = blockIdx.y * CHUNK;
    int pt = blockIdx.x;
    int p0 = pt * PTILE;

    float d[8][4];
#pragma unroll
    for (int j = 0; j < 8; j++)
#pragma unroll
        for (int i = 0; i < 4; i++) d[j][i] = 0.0f;

    float ur[8];
    auto ldgU = [&](int s) {
        int h0 = s * 32;
#pragma unroll
        for (int e = 0; e < 8; e++) {
            int idx = e * 256 + tid;
            int row = idx >> 5, k = idx & 31;
            ur[e] = u[(size_t)(l0 + row) * H_DIM + h0 + k];
        }
    };
    auto stU = [&]() {
#pragma unroll
        for (int e = 0; e < 8; e++) {
            int idx = e * 256 + tid;
            int row = idx >> 5, k = idx & 31;
            int c = k & 7;
            int off = (k >> 3) * 512 + row * 8 + (c & 3) * 2 + (c >> 2);
            float v = ur[e];
            float hi = s5_tf32_rna(v);
            xs[off] = hi;
            xs[2048 + off] = v - hi;
        }
    };
    auto cpW = [&](int s, int b) {
        float* wb = b ? wB1 : wB0;
        const float* src = &sc_WB[(size_t)(pt * 4 + s) * 4096];
#pragma unroll
        for (int e = 0; e < 4; e++) {
            int q = e * 256 + tid;
            s5_cp16(&wb[q * 4], &src[q * 4]);
        }
        s5_cpcommit();
    };

    ldgU(0);
    cpW(0, 0);
#pragma unroll
    for (int s = 0; s < 4; s++) {
        int b = s & 1;
        stU();
        if (s < 3) { ldgU(s + 1); cpW(s + 1, b ^ 1); }
        if (s < 3) s5_cpwait<1>(); else s5_cpwait<0>();
        __syncthreads();
        const float* wb = b ? wB1 : wB0;
#pragma unroll
        for (int k8 = 0; k8 < 4; k8++) {
            int arow = wm * 16 + gid;
            float2 ah0 = *(const float2*)(xs + k8 * 512 + arow * 8 + tig * 2);
            float2 ah1 = *(const float2*)(xs + k8 * 512 + (arow + 8) * 8 + tig * 2);
            float2 al0 = *(const float2*)(xs + 2048 + k8 * 512 + arow * 8 + tig * 2);
            float2 al1 = *(const float2*)(xs + 2048 + k8 * 512 + (arow + 8) * 8 + tig * 2);
            u32 ahi[4] = {__float_as_uint(ah0.x), __float_as_uint(ah1.x),
                          __float_as_uint(ah0.y), __float_as_uint(ah1.y)};
            u32 alo[4] = {__float_as_uint(al0.x), __float_as_uint(al1.x),
                          __float_as_uint(al0.y), __float_as_uint(al1.y)};
#pragma unroll
            for (int j = 0; j < 8; j++) {
                float2 bv = *(const float2*)(wb + k8 * 1024 + (wn * 64 + j * 8 + gid) * 8 + tig * 2);
                u32 b0 = __float_as_uint(bv.x), b1 = __float_as_uint(bv.y);
                S5_MMA(d[j], ahi, b0, b1);
                S5_MMA(d[j], alo, b0, b1);
            }
        }
        __syncthreads();
    }

    // write Bu tile (real cols: 2*pl + comp) into padded smem + dt
#pragma unroll
    for (int j = 0; j < 8; j++) {
        int cc = wn * 64 + j * 8 + tig * 2;
        int r1 = wm * 16 + gid;
        *(float2*)(Bu_s + r1 * BUS + cc)       = make_float2(d[j][0], d[j][1]);
        *(float2*)(Bu_s + (r1 + 8) * BUS + cc) = make_float2(d[j][2], d[j][3]);
    }
    if (tid < CHUNK) dt_s[tid] = dts[l0 + tid];
    __syncthreads();

    // ---- parallel local scan: 64 p-columns x 4 segments of 16 steps ----
    int p   = tid & 63;
    int seg = tid >> 6;
    int gp  = p0 + p;
    int lb  = seg * 16;
    float lre = Lre[gp], lim = Lim[gp];
    float step = expf(logstep[gp]);
    float inv = 1.0f / (lre * lre + lim * lim);

    float xrA[16], xiA[16], ArA[16], AiA[16];
    {
        float xr = 0.f, xi = 0.f, Ar = 1.f, Ai = 0.f;
#pragma unroll
        for (int j = 0; j < 16; j++) {
            float dd = dt_s[lb + j] * step;
            float ee = s5_exp_small(lre * dd);
            float sn, cs;
            s5_sincos(lim * dd, sn, cs);
            float ar = ee * cs, ai = ee * sn;
            float arm1 = ar - 1.0f;
            float gr = (arm1 * lre + ai * lim) * inv;
            float gi = (ai * lre - arm1 * lim) * inv;
            float2 bu = *(const float2*)(Bu_s + (lb + j) * BUS + 2 * p);
            float br  = gr * bu.x - gi * bu.y;
            float bi2 = gr * bu.y + gi * bu.x;
            float nxr = ar * xr - ai * xi + br;
            float nxi = ar * xi + ai * xr + bi2;
            xr = nxr; xi = nxi;
            float nAr = ar * Ar - ai * Ai;
            float nAi = ar * Ai + ai * Ar;
            Ar = nAr; Ai = nAi;
            xrA[j] = xr; xiA[j] = xi; ArA[j] = Ar; AiA[j] = Ai;
        }
        As_s[seg * 64 + p]  = make_float2(Ar, Ai);
        xs_s2[seg * 64 + p] = make_float2(xr, xi);
    }
    __syncthreads();

    float cr = 0.f, ci = 0.f, pr = 1.f, pi = 0.f;
    for (int s = 0; s < seg; s++) {
        float2 A  = As_s[s * 64 + p];
        float2 xe = xs_s2[s * 64 + p];
        float ncr = A.x * cr - A.y * ci + xe.x;
        float nci = A.x * ci + A.y * cr + xe.y;
        cr = ncr; ci = nci;
        float npr = A.x * pr - A.y * pi;
        float npi = A.x * pi + A.y * pr;
        pr = npr; pi = npi;
    }

#pragma unroll
    for (int j = 0; j < 16; j++) {
        float xgR = ArA[j] * cr - AiA[j] * ci + xrA[j];
        float xgI = ArA[j] * ci + AiA[j] * cr + xiA[j];
        sc_xloc[(size_t)(l0 + lb + j) * P_DIM + gp] = make_float2(xgR, xgI);
    }
    if (seg == 3) {
        float AgR = pr * ArA[15] - pi * AiA[15];
        float AgI = pr * AiA[15] + pi * ArA[15];
        float xeR = ArA[15] * cr - AiA[15] * ci + xrA[15];
        float xeI = ArA[15] * ci + AiA[15] * cr + xiA[15];
        sc_AchunkT[gp * NCHUNK + blockIdx.y] = make_float2(AgR, AgI);
        sc_xendT[gp * NCHUNK + blockIdx.y]   = make_float2(xeR, xeI);
    }
}

// ---------- S2: PARALLEL scan over chunk aggregates ----------
__global__ __launch_bounds__(512) void s5_k2_chunkscan() {
    __shared__ __align__(16) float4 sdat[NCHUNK];
    int p = blockIdx.x;
    int t = threadIdx.x;
    float2 A = sc_AchunkT[p * NCHUNK + t];
    float2 X = sc_xendT[p * NCHUNK + t];
    sdat[t] = make_float4(A.x, A.y, X.x, X.y);
    __syncthreads();
#pragma unroll
    for (int off = 1; off < NCHUNK; off <<= 1) {
        float4 prev;
        bool has = (t >= off);
        if (has) prev = sdat[t - off];
        __syncthreads();
        if (has) {
            float4 cur = sdat[t];
            float4 nw;
            nw.x = cur.x * prev.x - cur.y * prev.y;
            nw.y = cur.x * prev.y + cur.y * prev.x;
            nw.z = cur.x * prev.z - cur.y * prev.w + cur.z;
            nw.w = cur.x * prev.w + cur.y * prev.z + cur.w;
            sdat[t] = nw;
        }
        __syncthreads();
    }
    float2 carry = make_float2(0.f, 0.f);
    if (t > 0) {
        float4 v = sdat[t - 1];
        carry = make_float2(v.z, v.w);
    }
    sc_carry[t * P_DIM + p] = carry;
}

// ---------- S3: analytic-Acum fixup + TENSOR readout y = X@W + D*u ----------
__global__ __launch_bounds__(256, 2) void s5_k3_fixup_gemm(
    const float* __restrict__ u, const float* __restrict__ D, float* __restrict__ out) {
    __shared__ __align__(16) char smem[49152];
    float* xs  = (float*)smem;                        // X hi [0,2048) lo [2048,4096)
    float* wB0 = (float*)(smem + 16384);
    float* wB1 = (float*)(smem + 32768);

    int tid = threadIdx.x, tx = tid & 15, ty = tid >> 4;
    int lane = tid & 31, wid = tid >> 5;
    int gid = lane >> 2, tig = lane & 3;
    int wm = wid & 3, wn = wid >> 2;
    int chunk = blockIdx.x;
    int l0 = chunk * CHUNK;

    float d[8][4];
#pragma unroll
    for (int j = 0; j < 8; j++)
#pragma unroll
        for (int i = 0; i < 4; i++) d[j][i] = 0.0f;

    float2 Sr[4];
#pragma unroll
    for (int e = 0; e < 4; e++)
        Sr[e] = sc_S[chunk * CHUNK + 16 * e + ty];

    float2 pX[4], cC;
    float4 ab;
    auto ldgX = [&](int s) {
        int p0 = s * 16;
#pragma unroll
        for (int e = 0; e < 4; e++)
            pX[e] = sc_xloc[(size_t)(l0 + 16 * e + ty) * P_DIM + p0 + tx];
        cC = sc_carry[chunk * P_DIM + p0 + tx];
        ab = sc_ab4[p0 + tx];
    };
    auto stX = [&]() {
#pragma unroll
        for (int e = 0; e < 4; e++) {
            float Sh = Sr[e].x, Sl = Sr[e].y;
            float ph = ab.y * Sh;
            float pl = fmaf(ab.y, Sh, -ph);
            pl = fmaf(ab.y, Sl, pl);
            pl = fmaf(ab.z, Sh, pl);
            float amp = __expf(ab.x * Sh);
            float sn, cs;
            s5_sincos2(ph, pl, sn, cs);
            float Ar = amp * cs, Ai = amp * sn;
            float xre = Ar * cC.x - Ai * cC.y + pX[e].x;
            float xim = Ar * cC.y + Ai * cC.x + pX[e].y;
            int row = 16 * e + ty;
#pragma unroll
            for (int comp = 0; comp < 2; comp++) {
                float v = comp ? xim : xre;
                int k = comp * 16 + tx;
                int c = k & 7;
                int off = (k >> 3) * 512 + row * 8 + (c & 3) * 2 + (c >> 2);
                float hi = s5_tf32_rna(v);
                xs[off] = hi;
                xs[2048 + off] = v - hi;
            }
        }
    };
    auto cpW = [&](int s, int b) {
        float* wb = b ? wB1 : wB0;
        const float* src = &sc_Wt[s * 4096];
#pragma unroll
        for (int e = 0; e < 4; e++) {
            int q = e * 256 + tid;
            s5_cp16(&wb[q * 4], &src[q * 4]);
        }
        s5_cpcommit();
    };

    ldgX(0);
    cpW(0, 0);
    for (int s = 0; s < 16; s++) {
        int b = s & 1;
        stX();
        if (s < 15) { ldgX(s + 1); cpW(s + 1, b ^ 1); }
        if (s < 15) s5_cpwait<1>(); else s5_cpwait<0>();
        __syncthreads();
        const float* wb = b ? wB1 : wB0;
#pragma unroll
        for (int k8 = 0; k8 < 4; k8++) {
            int arow = wm * 16 + gid;
            float2 ah0 = *(const float2*)(xs + k8 * 512 + arow * 8 + tig * 2);
            float2 ah1 = *(const float2*)(xs + k8 * 512 + (arow + 8) * 8 + tig * 2);
            float2 al0 = *(const float2*)(xs + 2048 + k8 * 512 + arow * 8 + tig * 2);
            float2 al1 = *(const float2*)(xs + 2048 + k8 * 512 + (arow + 8) * 8 + tig * 2);
            u32 ahi[4] = {__float_as_uint(ah0.x), __float_as_uint(ah1.x),
                          __float_as_uint(ah0.y), __float_as_uint(ah1.y)};
            u32 alo[4] = {__float_as_uint(al0.x), __float_as_uint(al1.x),
                          __float_as_uint(al0.y), __float_as_uint(al1.y)};
#pragma unroll
            for (int j = 0; j < 8; j++) {
                float2 bv = *(const float2*)(wb + k8 * 1024 + (wn * 64 + j * 8 + gid) * 8 + tig * 2);
                u32 b0 = __float_as_uint(bv.x), b1 = __float_as_uint(bv.y);
                S5_MMA(d[j], ahi, b0, b1);
                S5_MMA(d[j], alo, b0, b1);
            }
        }
        __syncthreads();
    }

#pragma unroll
    for (int j = 0; j < 8; j++) {
        int h = wn * 64 + j * 8 + tig * 2;
        float2 Dv = *(const float2*)(D + h);
        int r1 = l0 + wm * 16 + gid;
        int r2 = r1 + 8;
        float2 u1 = *(const float2*)(u + (size_t)r1 * H_DIM + h);
        float2 u2 = *(const float2*)(u + (size_t)r2 * H_DIM + h);
        float2 y1, y2;
        y1.x = d[j][0] + Dv.x * u1.x;
        y1.y = d[j][1] + Dv.y * u1.y;
        y2.x = d[j][2] + Dv.x * u2.x;
        y2.y = d[j][3] + Dv.y * u2.y;
        *(float2*)(out + (size_t)r1 * H_DIM + h) = y1;
        *(float2*)(out + (size_t)r2 * H_DIM + h) = y2;
    }
}

extern "C" void kernel_launch(void* const* d_in, const int* in_sizes, int n_in,
                              void* d_out, int out_size) {
    const float* u       = (const float*)d_in[0];
    const float* dts     = (const float*)d_in[1];
    const float* Lre     = (const float*)d_in[2];
    const float* Lim     = (const float*)d_in[3];
    const float* logstep = (const float*)d_in[4];
    const float* Br      = (const float*)d_in[5];
    const float* Bi      = (const float*)d_in[6];
    const float* Cr      = (const float*)d_in[7];
    const float* Ci      = (const float*)d_in[8];
    const float* D       = (const float*)d_in[9];
    float* out = (float*)d_out;

    s5_k0_pack<<<(H_DIM * P_DIM + 255) / 256, 256>>>(Br, Bi, Cr, Ci, Lre, Lim, logstep);
    s5_kS_prefix<<<NCHUNK, CHUNK>>>(dts);
    dim3 g1(P_DIM / PTILE, L_SEQ / CHUNK);
    s5_k1_gemm_scan<<<g1, 256>>>(u, dts, Lre, Lim, logstep);
    s5_k2_chunkscan<<<P_DIM, NCHUNK>>>();
    s5_k3_fixup_gemm<<<L_SEQ / CHUNK, 256>>>(u, D, out);
}

// round 14
// speedup vs baseline: 2.0110x; 1.3130x over previous
#include <cuda_runtime.h>
#include <math.h>

#define L_SEQ 32768
#define H_DIM 128
#define P_DIM 256
#define CHUNK 64
#define NCHUNK (L_SEQ / CHUNK)   // 512
#define PTILE 64
#define BUS 136                   // padded float stride of Bu tile in smem

typedef unsigned long long u64;
typedef unsigned int u32;

// ---------- cp.async helpers ----------
__device__ __forceinline__ void s5_cp16(void* dst, const void* src) {
    unsigned d = (unsigned)__cvta_generic_to_shared(dst);
    asm volatile("cp.async.cg.shared.global [%0], [%1], 16;" :: "r"(d), "l"(src));
}
__device__ __forceinline__ void s5_cpcommit() {
    asm volatile("cp.async.commit_group;");
}
template <int N>
__device__ __forceinline__ void s5_cpwait() {
    asm volatile("cp.async.wait_group %0;" :: "n"(N));
}

// ---------- tf32 helpers ----------
__device__ __forceinline__ float s5_tf32_rna(float v) {
    u32 h;
    asm("cvt.rna.tf32.f32 %0, %1;" : "=r"(h) : "f"(v));
    return __uint_as_float(h);
}
#define S5_MMA(d, a, b0v, b1v) \
    asm volatile("mma.sync.aligned.m16n8k8.row.col.f32.tf32.tf32.f32 " \
                 "{%0,%1,%2,%3},{%4,%5,%6,%7},{%8,%9},{%0,%1,%2,%3};" \
                 : "+f"((d)[0]), "+f"((d)[1]), "+f"((d)[2]), "+f"((d)[3]) \
                 : "r"((a)[0]), "r"((a)[1]), "r"((a)[2]), "r"((a)[3]), \
                   "r"(b0v), "r"(b1v))

// ---------- fast math (validated ranges) ----------
__device__ __forceinline__ float s5_exp_small(float x) {   // x in [-0.06, 0]
    return fmaf(x, fmaf(x, fmaf(x, fmaf(x, 0.041666667f, 0.16666667f), 0.5f), 1.0f), 1.0f);
}
__device__ __forceinline__ void s5_sincos2(float x, float xlo, float& s_out, float& c_out) {
    float kf = rintf(x * 0.636619772f);                 // 2/pi
    float r = fmaf(-kf, 1.57079637f, x);
    r = fmaf(kf, 4.37113900e-8f, r);
    r += xlo;
    int q = (int)kf;
    float r2 = r * r;
    float sp = fmaf(r2, fmaf(r2, fmaf(r2, 2.7557314e-6f, -1.9841270e-4f),
                             8.3333310e-3f), -0.16666667f);
    sp = fmaf(r * r2, sp, r);
    float cp = fmaf(r2, fmaf(r2, fmaf(r2, 2.4801587e-5f, -1.3888889e-3f),
                             4.1666668e-2f), -0.5f);
    cp = fmaf(r2, cp, 1.0f);
    bool swp = (q & 1);
    float ss = swp ? cp : sp;
    float cc = swp ? sp : cp;
    if (q & 2) ss = -ss;
    if ((q + 1) & 2) cc = -cc;
    s_out = ss; c_out = cc;
}
__device__ __forceinline__ void s5_sincos(float x, float& s_out, float& c_out) {
    s5_sincos2(x, 0.0f, s_out, c_out);
}

// ---------- scratch (static device memory; no allocations) ----------
__device__ __align__(16) float2 sc_xloc[(size_t)L_SEQ * P_DIM];   // 64 MB
__device__ __align__(16) float2 sc_AchunkT[P_DIM * NCHUNK];       // [p][chunk]
__device__ __align__(16) float2 sc_xendT[P_DIM * NCHUNK];         // [p][chunk]
__device__ __align__(16) float2 sc_carry[NCHUNK * P_DIM];         // [chunk][p]
__device__ __align__(16) float2 sc_S[NCHUNK * CHUNK];             // dt prefix sums (hi, lo)
__device__ __align__(16) float4 sc_ab4[P_DIM];                    // (alpha, beta_hi, beta_lo, 0)
// k3 tensor operand: W = [2*Cr ; -2*Ci], tf32-RNE, fragment-permuted
__device__ __align__(16) float sc_Wt[16 * 4 * H_DIM * 8];         // 256 KB
// k1 tensor operand: WB[ptile(4)][s(4)][k8(4)][col(128)][sub(8)], col = 2*pl + (re/im)
__device__ __align__(16) float sc_WB[4 * 4 * 4 * 128 * 8];        // 256 KB

// ---------- S0: pack/permute operands; per-p discretization params ----------
__global__ void s5_k0_pack(const float* __restrict__ Br, const float* __restrict__ Bi,
                           const float* __restrict__ Cr, const float* __restrict__ Ci,
                           const float* __restrict__ Lre, const float* __restrict__ Lim,
                           const float* __restrict__ logstep) {
    int idx = blockIdx.x * blockDim.x + threadIdx.x;
    if (idx < H_DIM * P_DIM) {
        int h = idx & 127, p = idx >> 7;
        {   // Wt (k3 operand)
            int s = p >> 4, pp = p & 15;
            int c = pp & 7;
            int sub = (c & 3) * 2 + (c >> 2);
            int k8r = pp >> 3;
            int k8i = 2 + (pp >> 3);
            float cr = Cr[h * P_DIM + p];
            float ci = Ci[h * P_DIM + p];
            sc_Wt[s * 4096 + k8r * 1024 + h * 8 + sub] = s5_tf32_rna(2.0f * cr);
            sc_Wt[s * 4096 + k8i * 1024 + h * 8 + sub] = s5_tf32_rna(-2.0f * ci);
        }
        {   // WB (k1 operand)
            int pt = p >> 6, pl = p & 63;
            int s = h >> 5, hk = h & 31;
            int k8 = hk >> 3, c = hk & 7;
            int sub = (c & 3) * 2 + (c >> 2);
            size_t base = ((size_t)(pt * 4 + s) * 4 + k8) * 1024;
            sc_WB[base + (pl * 2 + 0) * 8 + sub] = s5_tf32_rna(Br[p * H_DIM + h]);
            sc_WB[base + (pl * 2 + 1) * 8 + sub] = s5_tf32_rna(Bi[p * H_DIM + h]);
        }
        if (idx < P_DIM) {
            float step = expf(logstep[idx]);
            float a  = Lre[idx] * step;
            float bh = Lim[idx] * step;
            float bl = fmaf(Lim[idx], step, -bh);
            sc_ab4[idx] = make_float4(a, bh, bl, 0.0f);
        }
    }
}

// ---------- S0b: per-chunk dt prefix sums in fp64, stored hi/lo ----------
__global__ void s5_kS_prefix(const float* __restrict__ dts) {
    __shared__ double s[CHUNK];
    int c = blockIdx.x, t = threadIdx.x;
    s[t] = (double)dts[c * CHUNK + t];
    __syncthreads();
#pragma unroll
    for (int off = 1; off < CHUNK; off <<= 1) {
        double add = (t >= off) ? s[t - off] : 0.0;
        __syncthreads();
        s[t] += add;
        __syncthreads();
    }
    double Sd = s[t];
    float hi = (float)Sd;
    float lo = (float)(Sd - (double)hi);
    sc_S[c * CHUNK + t] = make_float2(hi, lo);
}

// ---------- S1: TENSOR Bu = u @ [Br|Bi]^T, then 4-way-parallel local scan ----------
// hi-only tf32 activations (error budget calibrated: +~1.5e-5)
__global__ __launch_bounds__(256, 2) void s5_k1_gemm_scan(
    const float* __restrict__ u, const float* __restrict__ dts,
    const float* __restrict__ Lre, const float* __restrict__ Lim,
    const float* __restrict__ logstep) {
    __shared__ __align__(16) char smem[40960];
    float* xs  = (float*)smem;                        // u hi [0,8192)
    float* wB0 = (float*)(smem + 8192);               // WB slice buf 0 (16 KB)
    float* wB1 = (float*)(smem + 24576);
    // scan-phase aliases
    float* Bu_s  = (float*)smem;                      // 64 x BUS floats (34816 B)
    float* dt_s  = (float*)(smem + 34816);            // 256 B
    float2* As_s  = (float2*)(smem + 35072);          // 2 KB
    float2* xs_s2 = (float2*)(smem + 37120);          // 2 KB

    int tid = threadIdx.x;
    int lane = tid & 31, wid = tid >> 5;
    int gid = lane >> 2, tig = lane & 3;
    int wm = wid & 3, wn = wid >> 2;
    int l0 = blockIdx.y * CHUNK;
    int pt = blockIdx.x;
    int p0 = pt * PTILE;

    float d[8][4];
#pragma unroll
    for (int j = 0; j < 8; j++)
#pragma unroll
        for (int i = 0; i < 4; i++) d[j][i] = 0.0f;

    float ur[8];
    auto ldgU = [&](int s) {
        int h0 = s * 32;
#pragma unroll
        for (int e = 0; e < 8; e++) {
            int idx = e * 256 + tid;
            int row = idx >> 5, k = idx & 31;
            ur[e] = u[(size_t)(l0 + row) * H_DIM + h0 + k];
        }
    };
    auto stU = [&]() {
#pragma unroll
        for (int e = 0; e < 8; e++) {
            int idx = e * 256 + tid;
            int row = idx >> 5, k = idx & 31;
            int c = k & 7;
            int off = (k >> 3) * 512 + row * 8 + (c & 3) * 2 + (c >> 2);
            xs[off] = s5_tf32_rna(ur[e]);
        }
    };
    auto cpW = [&](int s, int b) {
        float* wb = b ? wB1 : wB0;
        const float* src = &sc_WB[(size_t)(pt * 4 + s) * 4096];
#pragma unroll
        for (int e = 0; e < 4; e++) {
            int q = e * 256 + tid;
            s5_cp16(&wb[q * 4], &src[q * 4]);
        }
        s5_cpcommit();
    };

    ldgU(0);
    cpW(0, 0);
#pragma unroll
    for (int s = 0; s < 4; s++) {
        int b = s & 1;
        stU();
        if (s < 3) { ldgU(s + 1); cpW(s + 1, b ^ 1); }
        if (s < 3) s5_cpwait<1>(); else s5_cpwait<0>();
        __syncthreads();
        const float* wb = b ? wB1 : wB0;
#pragma unroll
        for (int k8 = 0; k8 < 4; k8++) {
            int arow = wm * 16 + gid;
            float2 ah0 = *(const float2*)(xs + k8 * 512 + arow * 8 + tig * 2);
            float2 ah1 = *(const float2*)(xs + k8 * 512 + (arow + 8) * 8 + tig * 2);
            u32 ahi[4] = {__float_as_uint(ah0.x), __float_as_uint(ah1.x),
                          __float_as_uint(ah0.y), __float_as_uint(ah1.y)};
#pragma unroll
            for (int j = 0; j < 8; j++) {
                float2 bv = *(const float2*)(wb + k8 * 1024 + (wn * 64 + j * 8 + gid) * 8 + tig * 2);
                S5_MMA(d[j], ahi, __float_as_uint(bv.x), __float_as_uint(bv.y));
            }
        }
        __syncthreads();
    }

    // write Bu tile into padded smem + dt
#pragma unroll
    for (int j = 0; j < 8; j++) {
        int cc = wn * 64 + j * 8 + tig * 2;
        int r1 = wm * 16 + gid;
        *(float2*)(Bu_s + r1 * BUS + cc)       = make_float2(d[j][0], d[j][1]);
        *(float2*)(Bu_s + (r1 + 8) * BUS + cc) = make_float2(d[j][2], d[j][3]);
    }
    if (tid < CHUNK) dt_s[tid] = dts[l0 + tid];
    __syncthreads();

    // ---- parallel local scan: 64 p-columns x 4 segments of 16 steps ----
    int p   = tid & 63;
    int seg = tid >> 6;
    int gp  = p0 + p;
    int lb  = seg * 16;
    float lre = Lre[gp], lim = Lim[gp];
    float step = expf(logstep[gp]);
    float inv = 1.0f / (lre * lre + lim * lim);

    float xrA[16], xiA[16], ArA[16], AiA[16];
    {
        float xr = 0.f, xi = 0.f, Ar = 1.f, Ai = 0.f;
#pragma unroll
        for (int j = 0; j < 16; j++) {
            float dd = dt_s[lb + j] * step;
            float ee = s5_exp_small(lre * dd);
            float sn, cs;
            s5_sincos(lim * dd, sn, cs);
            float ar = ee * cs, ai = ee * sn;
            float arm1 = ar - 1.0f;
            float gr = (arm1 * lre + ai * lim) * inv;
            float gi = (ai * lre - arm1 * lim) * inv;
            float2 bu = *(const float2*)(Bu_s + (lb + j) * BUS + 2 * p);
            float br  = gr * bu.x - gi * bu.y;
            float bi2 = gr * bu.y + gi * bu.x;
            float nxr = ar * xr - ai * xi + br;
            float nxi = ar * xi + ai * xr + bi2;
            xr = nxr; xi = nxi;
            float nAr = ar * Ar - ai * Ai;
            float nAi = ar * Ai + ai * Ar;
            Ar = nAr; Ai = nAi;
            xrA[j] = xr; xiA[j] = xi; ArA[j] = Ar; AiA[j] = Ai;
        }
        As_s[seg * 64 + p]  = make_float2(Ar, Ai);
        xs_s2[seg * 64 + p] = make_float2(xr, xi);
    }
    __syncthreads();

    float cr = 0.f, ci = 0.f, pr = 1.f, pi = 0.f;
    for (int s = 0; s < seg; s++) {
        float2 A  = As_s[s * 64 + p];
        float2 xe = xs_s2[s * 64 + p];
        float ncr = A.x * cr - A.y * ci + xe.x;
        float nci = A.x * ci + A.y * cr + xe.y;
        cr = ncr; ci = nci;
        float npr = A.x * pr - A.y * pi;
        float npi = A.x * pi + A.y * pr;
        pr = npr; pi = npi;
    }

#pragma unroll
    for (int j = 0; j < 16; j++) {
        float xgR = ArA[j] * cr - AiA[j] * ci + xrA[j];
        float xgI = ArA[j] * ci + AiA[j] * cr + xiA[j];
        sc_xloc[(size_t)(l0 + lb + j) * P_DIM + gp] = make_float2(xgR, xgI);
    }
    if (seg == 3) {
        float AgR = pr * ArA[15] - pi * AiA[15];
        float AgI = pr * AiA[15] + pi * ArA[15];
        float xeR = ArA[15] * cr - AiA[15] * ci + xrA[15];
        float xeI = ArA[15] * ci + AiA[15] * cr + xiA[15];
        sc_AchunkT[gp * NCHUNK + blockIdx.y] = make_float2(AgR, AgI);
        sc_xendT[gp * NCHUNK + blockIdx.y]   = make_float2(xeR, xeI);
    }
}

// ---------- S2: PARALLEL scan over chunk aggregates ----------
__global__ __launch_bounds__(512) void s5_k2_chunkscan() {
    __shared__ __align__(16) float4 sdat[NCHUNK];
    int p = blockIdx.x;
    int t = threadIdx.x;
    float2 A = sc_AchunkT[p * NCHUNK + t];
    float2 X = sc_xendT[p * NCHUNK + t];
    sdat[t] = make_float4(A.x, A.y, X.x, X.y);
    __syncthreads();
#pragma unroll
    for (int off = 1; off < NCHUNK; off <<= 1) {
        float4 prev;
        bool has = (t >= off);
        if (has) prev = sdat[t - off];
        __syncthreads();
        if (has) {
            float4 cur = sdat[t];
            float4 nw;
            nw.x = cur.x * prev.x - cur.y * prev.y;
            nw.y = cur.x * prev.y + cur.y * prev.x;
            nw.z = cur.x * prev.z - cur.y * prev.w + cur.z;
            nw.w = cur.x * prev.w + cur.y * prev.z + cur.w;
            sdat[t] = nw;
        }
        __syncthreads();
    }
    float2 carry = make_float2(0.f, 0.f);
    if (t > 0) {
        float4 v = sdat[t - 1];
        carry = make_float2(v.z, v.w);
    }
    sc_carry[t * P_DIM + p] = carry;
}

// ---------- S3: analytic-Acum fixup + TENSOR readout y = X@W + D*u ----------
__global__ __launch_bounds__(256, 2) void s5_k3_fixup_gemm(
    const float* __restrict__ u, const float* __restrict__ D, float* __restrict__ out) {
    __shared__ __align__(16) char smem[40960];
    float* xs  = (float*)smem;                        // X hi [0,8192)
    float* wB0 = (float*)(smem + 8192);
    float* wB1 = (float*)(smem + 24576);

    int tid = threadIdx.x, tx = tid & 15, ty = tid >> 4;
    int lane = tid & 31, wid = tid >> 5;
    int gid = lane >> 2, tig = lane & 3;
    int wm = wid & 3, wn = wid >> 2;
    int chunk = blockIdx.x;
    int l0 = chunk * CHUNK;

    float d[8][4];
#pragma unroll
    for (int j = 0; j < 8; j++)
#pragma unroll
        for (int i = 0; i < 4; i++) d[j][i] = 0.0f;

    float2 Sr[4];
#pragma unroll
    for (int e = 0; e < 4; e++)
        Sr[e] = sc_S[chunk * CHUNK + 16 * e + ty];

    float2 pX[4], cC;
    float4 ab;
    auto ldgX = [&](int s) {
        int p0 = s * 16;
#pragma unroll
        for (int e = 0; e < 4; e++)
            pX[e] = sc_xloc[(size_t)(l0 + 16 * e + ty) * P_DIM + p0 + tx];
        cC = sc_carry[chunk * P_DIM + p0 + tx];
        ab = sc_ab4[p0 + tx];
    };
    auto stX = [&]() {
#pragma unroll
        for (int e = 0; e < 4; e++) {
            float Sh = Sr[e].x, Sl = Sr[e].y;
            float ph = ab.y * Sh;
            float pl = fmaf(ab.y, Sh, -ph);
            pl = fmaf(ab.y, Sl, pl);
            pl = fmaf(ab.z, Sh, pl);
            float amp = __expf(ab.x * Sh);
            float sn, cs;
            s5_sincos2(ph, pl, sn, cs);
            float Ar = amp * cs, Ai = amp * sn;
            float xre = Ar * cC.x - Ai * cC.y + pX[e].x;
            float xim = Ar * cC.y + Ai * cC.x + pX[e].y;
            int row = 16 * e + ty;
#pragma unroll
            for (int comp = 0; comp < 2; comp++) {
                float v = comp ? xim : xre;
                int k = comp * 16 + tx;
                int c = k & 7;
                int off = (k >> 3) * 512 + row * 8 + (c & 3) * 2 + (c >> 2);
                xs[off] = s5_tf32_rna(v);
            }
        }
    };
    auto cpW = [&](int s, int b) {
        float* wb = b ? wB1 : wB0;
        const float* src = &sc_Wt[s * 4096];
#pragma unroll
        for (int e = 0; e < 4; e++) {
            int q = e * 256 + tid;
            s5_cp16(&wb[q * 4], &src[q * 4]);
        }
        s5_cpcommit();
    };

    ldgX(0);
    cpW(0, 0);
    for (int s = 0; s < 16; s++) {
        int b = s & 1;
        stX();
        if (s < 15) { ldgX(s + 1); cpW(s + 1, b ^ 1); }
        if (s < 15) s5_cpwait<1>(); else s5_cpwait<0>();
        __syncthreads();
        const float* wb = b ? wB1 : wB0;
#pragma unroll
        for (int k8 = 0; k8 < 4; k8++) {
            int arow = wm * 16 + gid;
            float2 ah0 = *(const float2*)(xs + k8 * 512 + arow * 8 + tig * 2);
            float2 ah1 = *(const float2*)(xs + k8 * 512 + (arow + 8) * 8 + tig * 2);
            u32 ahi[4] = {__float_as_uint(ah0.x), __float_as_uint(ah1.x),
                          __float_as_uint(ah0.y), __float_as_uint(ah1.y)};
#pragma unroll
            for (int j = 0; j < 8; j++) {
                float2 bv = *(const float2*)(wb + k8 * 1024 + (wn * 64 + j * 8 + gid) * 8 + tig * 2);
                S5_MMA(d[j], ahi, __float_as_uint(bv.x), __float_as_uint(bv.y));
            }
        }
        __syncthreads();
    }

#pragma unroll
    for (int j = 0; j < 8; j++) {
        int h = wn * 64 + j * 8 + tig * 2;
        float2 Dv = *(const float2*)(D + h);
        int r1 = l0 + wm * 16 + gid;
        int r2 = r1 + 8;
        float2 u1 = *(const float2*)(u + (size_t)r1 * H_DIM + h);
        float2 u2 = *(const float2*)(u + (size_t)r2 * H_DIM + h);
        float2 y1, y2;
        y1.x = d[j][0] + Dv.x * u1.x;
        y1.y = d[j][1] + Dv.y * u1.y;
        y2.x = d[j][2] + Dv.x * u2.x;
        y2.y = d[j][3] + Dv.y * u2.y;
        *(float2*)(out + (size_t)r1 * H_DIM + h) = y1;
        *(float2*)(out + (size_t)r2 * H_DIM + h) = y2;
    }
}

extern "C" void kernel_launch(void* const* d_in, const int* in_sizes, int n_in,
                              void* d_out, int out_size) {
    const float* u       = (const float*)d_in[0];
    const float* dts     = (const float*)d_in[1];
    const float* Lre     = (const float*)d_in[2];
    const float* Lim     = (const float*)d_in[3];
    const float* logstep = (const float*)d_in[4];
    const float* Br      = (const float*)d_in[5];
    const float* Bi      = (const float*)d_in[6];
    const float* Cr      = (const float*)d_in[7];
    const float* Ci      = (const float*)d_in[8];
    const float* D       = (const float*)d_in[9];
    float* out = (float*)d_out;

    s5_k0_pack<<<(H_DIM * P_DIM + 255) / 256, 256>>>(Br, Bi, Cr, Ci, Lre, Lim, logstep);
    s5_kS_prefix<<<NCHUNK, CHUNK>>>(dts);
    dim3 g1(P_DIM / PTILE, L_SEQ / CHUNK);
    s5_k1_gemm_scan<<<g1, 256>>>(u, dts, Lre, Lim, logstep);
    s5_k2_chunkscan<<<P_DIM, NCHUNK>>>();
    s5_k3_fixup_gemm<<<L_SEQ / CHUNK, 256>>>(u, D, out);
}